// round 11
// baseline (speedup 1.0000x reference)
#include <cuda_runtime.h>
#include <math.h>

// Problem dims: B=4 O=4 L=128 N=8 V=256 H=256, Ls=2L=256, BO=16, BON=128, NL=1024

// ---------------- scratch (device globals; no allocation allowed) ----------------
__device__ float g_stmt_in[16 * 256 * 256];
__device__ float g_xg_stmt[16 * 256 * 768];
__device__ float g_stmt_h[16 * 256 * 256];
__device__ float g_xg_docs[128 * 128 * 768];
__device__ float g_docs_h[128 * 128 * 256];
__device__ float g_hs0[16 * 256], g_hs1[16 * 256];
__device__ float g_hd0[128 * 256], g_hd1[128 * 256];
__device__ float g_match[128 * 256 * 128];
__device__ float g_p1[128 * 256 * 128];
__device__ float g_p2t[128 * 128 * 256];
__device__ float g_read_sum[128 * 256 * 256];
__device__ float g_doc_read[128 * 128 * 256];
__device__ float g_dri[128 * 128 * 512];
__device__ float g_mm[16 * 1024 * 1024];
__device__ float g_att[128 * 128 * 512];
__device__ float g_xg_sr[128 * 256 * 768];
__device__ float g_xg_dr[128 * 128 * 768];
__device__ float g_hsr0[128 * 256], g_hsr1[128 * 256];
__device__ float g_hdr0[128 * 256], g_hdr1[128 * 256];
__device__ float g_srmax[128 * 256], g_drmax[128 * 256];

// per-(slot, chunk) monotonic step flags: 64 slots x 8 chunks, 128B stride
__device__ unsigned g_flag[64 * 8 * 32];

// ---------------- init ----------------
__global__ void init_state() {
    int i = blockIdx.x * 256 + threadIdx.x;  // 32768 threads
    if (i < 64 * 8 * 32) g_flag[i] = 0u;
    if (i < 16 * 256) { g_hs0[i] = 0.f; g_hs1[i] = 0.f; }
    if (i < 128 * 256) {
        g_hd0[i] = 0.f;  g_hd1[i] = 0.f;
        g_hsr0[i] = 0.f; g_hsr1[i] = 0.f;
        g_hdr0[i] = 0.f; g_hdr1[i] = 0.f;
    }
}

// ---------------- build stmt = cat(question, answer) ----------------
__global__ void concat_stmt(const float* __restrict__ statement,
                            const float* __restrict__ answer) {
    int idx = blockIdx.x * 256 + threadIdx.x;  // 1048576
    int v = idx & 255;
    int s = (idx >> 8) & 255;
    int bo = idx >> 16;
    int b = bo >> 2;
    float val;
    if (s < 128) val = statement[(b * 128 + s) * 256 + v];
    else         val = answer[(bo * 128 + (s - 128)) * 256 + v];
    g_stmt_in[idx] = val;
}

// ---------------- dri = cat(docs, doc_read) ----------------
__global__ void concat_dri() {
    for (int idx = blockIdx.x * blockDim.x + threadIdx.x; idx < 128 * 128 * 512;
         idx += gridDim.x * blockDim.x) {
        int h = idx & 511;
        int rest = idx >> 9;
        g_dri[idx] = (h < 256) ? g_docs_h[rest * 256 + h]
                               : g_doc_read[rest * 256 + (h - 256)];
    }
}

// ---------------- tf32 tensor-core GEMM ----------------
__device__ __forceinline__ unsigned f2tf(float x) {
    unsigned r;
    asm("cvt.rna.tf32.f32 %0, %1;" : "=r"(r) : "f"(x));
    return r;
}

__device__ __forceinline__ void mma_tf32(float4& d, const unsigned* a, const unsigned* b) {
    asm volatile(
        "mma.sync.aligned.m16n8k8.row.col.f32.tf32.tf32.f32 "
        "{%0,%1,%2,%3}, {%4,%5,%6,%7}, {%8,%9}, {%0,%1,%2,%3};"
        : "+f"(d.x), "+f"(d.y), "+f"(d.z), "+f"(d.w)
        : "r"(a[0]), "r"(a[1]), "r"(a[2]), "r"(a[3]), "r"(b[0]), "r"(b[1]));
}

// Tile 128x128, K-tile 32, 256 threads (8 warps, each 64x32).
// TB=1: C = A[M,K] * B[N,K]^T (+bias);  TB=0: C = A[M,K] * B[K,N] (+bias)
template <int TB>
__global__ void __launch_bounds__(256) gemm_tf32(
    const float* __restrict__ A, const float* __restrict__ B,
    const float* __restrict__ bias, float* __restrict__ C,
    int N, int K, long long sA, long long sB, long long sC,
    int divA, int divB) {
    const int tid = threadIdx.x;
    int z = blockIdx.z;
    A += (long long)(z / divA) * sA + (long long)(blockIdx.y * 128) * K;
    if (TB) B += (long long)(z / divB) * sB + (long long)(blockIdx.x * 128) * K;
    else    B += (long long)(z / divB) * sB + blockIdx.x * 128;
    C += (long long)z * sC + (long long)(blockIdx.y * 128) * N + blockIdx.x * 128;

    __shared__ unsigned As[128 * 36];   // [m][k], pitch 36 -> conflict-free frags
    __shared__ unsigned Bs[128 * 36];   // TN: [n][k] pitch 36; NN: [k][n] pitch 132

    const int warp = tid >> 5, lane = tid & 31;
    const int wm = (warp & 1) * 64, wn = (warp >> 1) * 32;
    const int lq = lane >> 2, lr = lane & 3;

    const int sm = tid >> 3;         // 0..31 (row group, +32*i)
    const int sk = (tid & 7) * 4;    // 0..28
    const int bk = tid >> 5;         // 0..7 (NN k row, +8*i)
    const int bn = (tid & 31) * 4;   // 0..124

    float4 acc[4][4];
#pragma unroll
    for (int i = 0; i < 4; i++)
#pragma unroll
        for (int j = 0; j < 4; j++) acc[i][j] = make_float4(0.f, 0.f, 0.f, 0.f);

    float4 pa[4], pb[4];
#pragma unroll
    for (int i = 0; i < 4; i++)
        pa[i] = *reinterpret_cast<const float4*>(&A[(long long)(sm + 32 * i) * K + sk]);
    if (TB) {
#pragma unroll
        for (int i = 0; i < 4; i++)
            pb[i] = *reinterpret_cast<const float4*>(&B[(long long)(sm + 32 * i) * K + sk]);
    } else {
#pragma unroll
        for (int i = 0; i < 4; i++)
            pb[i] = *reinterpret_cast<const float4*>(&B[(long long)(bk + 8 * i) * N + bn]);
    }

    int k0 = 0;
    for (;;) {
#pragma unroll
        for (int i = 0; i < 4; i++) {
            uint4 u;
            u.x = f2tf(pa[i].x); u.y = f2tf(pa[i].y); u.z = f2tf(pa[i].z); u.w = f2tf(pa[i].w);
            *reinterpret_cast<uint4*>(&As[(sm + 32 * i) * 36 + sk]) = u;
        }
#pragma unroll
        for (int i = 0; i < 4; i++) {
            uint4 u;
            u.x = f2tf(pb[i].x); u.y = f2tf(pb[i].y); u.z = f2tf(pb[i].z); u.w = f2tf(pb[i].w);
            if (TB) *reinterpret_cast<uint4*>(&Bs[(sm + 32 * i) * 36 + sk]) = u;
            else    *reinterpret_cast<uint4*>(&Bs[(bk + 8 * i) * 132 + bn]) = u;
        }
        __syncthreads();

        int k1 = k0 + 32;
        if (k1 < K) {
#pragma unroll
            for (int i = 0; i < 4; i++)
                pa[i] = *reinterpret_cast<const float4*>(&A[(long long)(sm + 32 * i) * K + k1 + sk]);
            if (TB) {
#pragma unroll
                for (int i = 0; i < 4; i++)
                    pb[i] = *reinterpret_cast<const float4*>(&B[(long long)(sm + 32 * i) * K + k1 + sk]);
            } else {
#pragma unroll
                for (int i = 0; i < 4; i++)
                    pb[i] = *reinterpret_cast<const float4*>(&B[(long long)(k1 + bk + 8 * i) * N + bn]);
            }
        }

#pragma unroll
        for (int kk = 0; kk < 32; kk += 8) {
            unsigned a[4][4];
#pragma unroll
            for (int mt = 0; mt < 4; mt++) {
                int r = (wm + mt * 16 + lq) * 36 + kk + lr;
                a[mt][0] = As[r];
                a[mt][1] = As[r + 8 * 36];
                a[mt][2] = As[r + 4];
                a[mt][3] = As[r + 8 * 36 + 4];
            }
            unsigned b[4][2];
#pragma unroll
            for (int nt = 0; nt < 4; nt++) {
                if (TB) {
                    int r = (wn + nt * 8 + lq) * 36 + kk + lr;
                    b[nt][0] = Bs[r];
                    b[nt][1] = Bs[r + 4];
                } else {
                    int r = (kk + lr) * 132 + wn + nt * 8 + lq;
                    b[nt][0] = Bs[r];
                    b[nt][1] = Bs[r + 4 * 132];
                }
            }
#pragma unroll
            for (int mt = 0; mt < 4; mt++)
#pragma unroll
                for (int nt = 0; nt < 4; nt++) mma_tf32(acc[mt][nt], a[mt], b[nt]);
        }
        if (k1 >= K) break;
        __syncthreads();
        k0 = k1;
    }

#pragma unroll
    for (int nt = 0; nt < 4; nt++) {
        int col = wn + nt * 8 + 2 * lr;
        float bx = 0.f, by = 0.f;
        if (bias) {
            int cg = blockIdx.x * 128 + col;
            bx = bias[cg]; by = bias[cg + 1];
        }
#pragma unroll
        for (int mt = 0; mt < 4; mt++) {
            int row = wm + mt * 16 + lq;
            float4 v = acc[mt][nt];
            float2 v0 = make_float2(v.x + bx, v.y + by);
            float2 v1 = make_float2(v.z + bx, v.w + by);
            *reinterpret_cast<float2*>(&C[(long long)row * N + col]) = v0;
            *reinterpret_cast<float2*>(&C[(long long)(row + 8) * N + col]) = v1;
        }
    }
}

// ---------------- softmax: 1024 cols, block per row, regs-resident ----------------
__global__ void __launch_bounds__(256) softmax_block1024(const float* __restrict__ in,
                                                         float* __restrict__ out) {
    long long row = blockIdx.x;
    const float4* x = reinterpret_cast<const float4*>(in + row * 1024);
    float4* y = reinterpret_cast<float4*>(out + row * 1024);
    int tid = threadIdx.x, warp = tid >> 5, lane = tid & 31;
    __shared__ float redm[8], reds[8];
    float4 v = x[tid];
    float m = fmaxf(fmaxf(v.x, v.y), fmaxf(v.z, v.w));
#pragma unroll
    for (int off = 16; off; off >>= 1) m = fmaxf(m, __shfl_xor_sync(0xffffffffu, m, off));
    if (lane == 0) redm[warp] = m;
    __syncthreads();
    m = redm[0];
#pragma unroll
    for (int i = 1; i < 8; i++) m = fmaxf(m, redm[i]);
    v.x = __expf(v.x - m); v.y = __expf(v.y - m); v.z = __expf(v.z - m); v.w = __expf(v.w - m);
    float s = v.x + v.y + v.z + v.w;
#pragma unroll
    for (int off = 16; off; off >>= 1) s += __shfl_xor_sync(0xffffffffu, s, off);
    if (lane == 0) reds[warp] = s;
    __syncthreads();
    s = reds[0];
#pragma unroll
    for (int i = 1; i < 8; i++) s += reds[i];
    float inv = 1.f / s;
    v.x *= inv; v.y *= inv; v.z *= inv; v.w *= inv;
    y[tid] = v;
}

// ---------------- softmax: 128 cols, warp per row (8 rows per block) ----------------
__global__ void __launch_bounds__(256) softmax_warp128(const float* __restrict__ in,
                                                       float* __restrict__ out) {
    int warp = threadIdx.x >> 5, lane = threadIdx.x & 31;
    long long row = (long long)blockIdx.x * 8 + warp;
    const float4* x = reinterpret_cast<const float4*>(in + row * 128);
    float4* y = reinterpret_cast<float4*>(out + row * 128);
    float4 v = x[lane];
    float m = fmaxf(fmaxf(v.x, v.y), fmaxf(v.z, v.w));
#pragma unroll
    for (int off = 16; off; off >>= 1) m = fmaxf(m, __shfl_xor_sync(0xffffffffu, m, off));
    v.x = __expf(v.x - m); v.y = __expf(v.y - m); v.z = __expf(v.z - m); v.w = __expf(v.w - m);
    float s = v.x + v.y + v.z + v.w;
#pragma unroll
    for (int off = 16; off; off >>= 1) s += __shfl_xor_sync(0xffffffffu, s, off);
    float inv = 1.f / s;
    v.x *= inv; v.y *= inv; v.z *= inv; v.w *= inv;
    y[lane] = v;
}

// ---------------- column softmax of match over s, output transposed [bon][l][s] ----------------
__global__ void __launch_bounds__(128) softmax_cols_t() {
    int bon = blockIdx.y;
    int l = blockIdx.x * 4 + (threadIdx.x >> 5);
    int lane = threadIdx.x & 31;
    const float* base = g_match + (long long)bon * 256 * 128 + l;
    float v[8];
    float m = -1e30f;
#pragma unroll
    for (int i = 0; i < 8; i++) {
        v[i] = base[(lane + 32 * i) * 128];
        m = fmaxf(m, v[i]);
    }
#pragma unroll
    for (int off = 16; off; off >>= 1) m = fmaxf(m, __shfl_xor_sync(0xffffffffu, m, off));
    float sum = 0.f;
#pragma unroll
    for (int i = 0; i < 8; i++) { v[i] = __expf(v[i] - m); sum += v[i]; }
#pragma unroll
    for (int off = 16; off; off >>= 1) sum += __shfl_xor_sync(0xffffffffu, sum, off);
    float inv = 1.f / sum;
    float* o = g_p2t + ((long long)bon * 128 + l) * 256;
#pragma unroll
    for (int i = 0; i < 8; i++) o[lane + 32 * i] = v[i] * inv;
}

// ---------------- acquire/relaxed flag ops ----------------
__device__ __forceinline__ unsigned ld_acq(const unsigned* p) {
    unsigned v;
    asm volatile("ld.global.acquire.gpu.u32 %0, [%1];" : "=r"(v) : "l"(p) : "memory");
    return v;
}
__device__ __forceinline__ void st_rlx(unsigned* p, unsigned v) {
    asm volatile("st.global.relaxed.gpu.u32 [%0], %1;" :: "l"(p), "r"(v) : "memory");
}

// ---------------- persistent fused GRU phase (dual-lane ping-pong) ----------------
struct GG {
    const float* xg;    // [nseq][T][768]
    const float* whh;   // [768][256]
    const float* bhh;   // [768]
    float* h0;          // [nseq][256] (t even input)
    float* h1;
    float* ys;          // optional [nseq][T][256]
    float* hmax;        // optional [nseq][256]
    int T;
    int nsg;            // seq groups of EIGHT (even count; lanes pair 2 groups)
    int slotbase;       // flag slot base (one slot per sgrp)
};

#define WP 260  // weight row pitch (floats) -> conflict-free 8-row 16B frags
#define HP 260  // h row pitch

// packed fp32x2 FMA (sm_10x): acc{lo,hi} += a{lo,hi} * b{lo,hi}
#define FMA2(acc, a, b) \
    asm("fma.rn.f32x2 %0, %1, %2, %0;" : "+l"(acc) : "l"(a), "l"(b))
#define UNPK(lo, hi, v) \
    asm("mov.b64 {%0,%1}, %2;" : "=f"(lo), "=f"(hi) : "l"(v))

__device__ __forceinline__ float red2(unsigned long long a, unsigned long long b) {
    float l0, h0, l1, h1;
    UNPK(l0, h0, a); UNPK(l1, h1, b);
    return (l0 + h0) + (l1 + h1);
}

// block = 256 threads (8 warps), handles TWO 8-seq lanes of the SAME group and
// ONE 32-col chunk. col-warp cw = warp&3 owns 8 cols; k-warp kw = warp>>2 does
// half the k range. lane thread cells: col = chunk*32 + cw*8 + (lane&7),
// seqs (lane>>3) + 4*j, j in {0,1}. Ping-pong between the two sequence lanes
// hides the flag round-trip + h L2 reload behind the other lane's compute.
__global__ void __launch_bounds__(256) gru_phase(GG ga, GG gb) {
    extern __shared__ float sm[];
    float* ws = sm;                        // 96 x WP
    float* hs = sm + 96 * WP;              // 8 x HP (shared by lanes, serialized)
    float* red = sm + 96 * WP + 8 * HP;    // 128 x 7 (pad-7: conflict-free)

    GG g;
    int sg0, mychunk;
    {
        int b = blockIdx.x;
        int blocks0 = (ga.nsg >> 1) * 8;
        if (b < blocks0) { g = ga; sg0 = (b >> 3) * 2; mychunk = b & 7; }
        else { int bb = b - blocks0; g = gb; sg0 = (bb >> 3) * 2; mychunk = bb & 7; }
    }
    const int colbase = mychunk * 32;
    const int tid = threadIdx.x;
    const int warp = tid >> 5, lane = tid & 31;
    const int kw = warp >> 2, cw = warp & 3;
    const int c8 = lane & 7, sq = lane >> 3;
    const int widx = cw * 8 + c8;   // col within chunk, 0..31
    const int col = colbase + widx;

    // load weight slice: ws row r = gate*32 + j holds whh[gate*256 + colbase + j][:]
    for (int i = tid; i < 96 * 64; i += 256) {
        int r = i >> 6, q = i & 63;
        float4 v = __ldg(reinterpret_cast<const float4*>(
            &g.whh[(long long)((r >> 5) * 256 + colbase + (r & 31)) * 256 + q * 4]));
        *reinterpret_cast<float4*>(&ws[r * WP + q * 4]) = v;
    }
    const float br = g.bhh[col], bz = g.bhh[256 + col], bn = g.bhh[512 + col];
    float mx[2][2] = {{-1e30f, -1e30f}, {-1e30f, -1e30f}};

    const ulonglong2* wR = reinterpret_cast<const ulonglong2*>(&ws[(0  + widx) * WP]);
    const ulonglong2* wZ = reinterpret_cast<const ulonglong2*>(&ws[(32 + widx) * WP]);
    const ulonglong2* wN = reinterpret_cast<const ulonglong2*>(&ws[(64 + widx) * WP]);
    const ulonglong2* hr0 = reinterpret_cast<const ulonglong2*>(&hs[sq * HP]);
    const ulonglong2* hr1 = reinterpret_cast<const ulonglong2*>(&hs[(sq + 4) * HP]);

    const int q0 = kw * 32, q1 = q0 + 32;   // half of the 64 ulonglong2 k-units
    const int T = g.T;
    __syncthreads();  // ws ready

    for (int t = 0; t < T; t++) {
#pragma unroll
        for (int ln = 0; ln < 2; ln++) {
            const int sgrp = sg0 + ln;
            unsigned* flags = &g_flag[(g.slotbase + sgrp) * 8 * 32];
            // wait for this lane's previous step globally (published one
            // lane-compute ago -> normally already satisfied)
            if (t > 0 && tid < 8) {
                while (ld_acq(&flags[tid * 32]) < (unsigned)t) {}
            }
            __syncthreads();  // wait done + hs free (prev lane finished reading)

            const float* hin = (t & 1) ? g.h1 : g.h0;
            float* hout = (t & 1) ? g.h0 : g.h1;
            const float4* tb =
                reinterpret_cast<const float4*>(hin + (long long)sgrp * 8 * 256);
            // stage h tile [8][256]: 512 float4 over 256 threads
#pragma unroll
            for (int i = 0; i < 2; i++) {
                int idx = tid + i * 256;  // seq = idx>>6, unit = idx&63
                float4 v = __ldcg(tb + idx);
                *reinterpret_cast<float4*>(&hs[(idx >> 6) * HP + (idx & 63) * 4]) = v;
            }
            // xg prefetch (kw==0 threads consume)
            float xr[2], xz[2], xn[2];
            if (kw == 0) {
#pragma unroll
                for (int j = 0; j < 2; j++) {
                    long long base =
                        ((long long)(sgrp * 8 + sq + 4 * j) * T + t) * 768;
                    xr[j] = __ldg(&g.xg[base + col]);
                    xz[j] = __ldg(&g.xg[base + 256 + col]);
                    xn[j] = __ldg(&g.xg[base + 512 + col]);
                }
            }
            __syncthreads();  // hs staged

            unsigned long long aR[2][2], aZ[2][2], aN[2][2];
#pragma unroll
            for (int j = 0; j < 2; j++) {
                aR[j][0] = aR[j][1] = 0ull;
                aZ[j][0] = aZ[j][1] = 0ull;
                aN[j][0] = aN[j][1] = 0ull;
            }
#pragma unroll 4
            for (int q = q0; q < q1; q++) {
                ulonglong2 r_ = wR[q], z_ = wZ[q], n_ = wN[q];
                ulonglong2 h0 = hr0[q], h1 = hr1[q];
                FMA2(aR[0][0], r_.x, h0.x); FMA2(aR[0][1], r_.y, h0.y);
                FMA2(aZ[0][0], z_.x, h0.x); FMA2(aZ[0][1], z_.y, h0.y);
                FMA2(aN[0][0], n_.x, h0.x); FMA2(aN[0][1], n_.y, h0.y);
                FMA2(aR[1][0], r_.x, h1.x); FMA2(aR[1][1], r_.y, h1.y);
                FMA2(aZ[1][0], z_.x, h1.x); FMA2(aZ[1][1], z_.y, h1.y);
                FMA2(aN[1][0], n_.x, h1.x); FMA2(aN[1][1], n_.y, h1.y);
            }
            float pr[2], pz[2], pn[2];
#pragma unroll
            for (int j = 0; j < 2; j++) {
                pr[j] = red2(aR[j][0], aR[j][1]);
                pz[j] = red2(aZ[j][0], aZ[j][1]);
                pn[j] = red2(aN[j][0], aN[j][1]);
            }
            // merge kw halves through smem
            if (kw == 1) {
                float* rp = &red[(tid - 128) * 7];
#pragma unroll
                for (int j = 0; j < 2; j++) {
                    rp[j] = pr[j]; rp[2 + j] = pz[j]; rp[4 + j] = pn[j];
                }
            }
            __syncthreads();  // partials ready
            if (kw == 0) {
                const float* rp = &red[tid * 7];
#pragma unroll
                for (int j = 0; j < 2; j++) {
                    int sl = sq + 4 * j;
                    long long seq = sgrp * 8 + sl;
                    float hrv = pr[j] + rp[j] + br;
                    float hzv = pz[j] + rp[2 + j] + bz;
                    float hnv = pn[j] + rp[4 + j] + bn;
                    float r = 1.f / (1.f + expf(-(xr[j] + hrv)));
                    float z = 1.f / (1.f + expf(-(xz[j] + hzv)));
                    float n = tanhf(xn[j] + r * hnv);
                    float hold = hs[sl * HP + col];
                    float h = (1.f - z) * n + z * hold;
                    hout[seq * 256 + col] = h;
                    if (g.ys) g.ys[(seq * T + t) * 256 + col] = h;
                    mx[ln][j] = fmaxf(mx[ln][j], h);
                }
            }
            __syncthreads();  // all h stores issued before publish; hs reusable
            if (tid == 0 && t + 1 < T) {
                __threadfence();                       // order h stores before flag
                st_rlx(&flags[mychunk * 32], (unsigned)(t + 1));
            }
        }
    }
    if (g.hmax && kw == 0) {
#pragma unroll
        for (int ln = 0; ln < 2; ln++)
#pragma unroll
            for (int j = 0; j < 2; j++) {
                long long seq = (long long)(sg0 + ln) * 8 + sq + 4 * j;
                g.hmax[seq * 256 + col] = mx[ln][j];
            }
    }
}

// ---------------- final: coef gate, feat, output head, softmax over options ----------------
__global__ void __launch_bounds__(512) final_kernel(
    const float* __restrict__ gate_w, const float* __restrict__ gate_b,
    const float* __restrict__ out_w, const float* __restrict__ out_b,
    float* __restrict__ out) {
    __shared__ float coef[128];
    __shared__ float logits[16];
    int tid = threadIdx.x, w = tid >> 5, lane = tid & 31;
    for (int bon = w; bon < 128; bon += 16) {
        float s = 0.f;
        for (int d = lane; d < 512; d += 32) {
            float rv = (d < 256) ? g_srmax[bon * 256 + d] : g_drmax[bon * 256 + d - 256];
            s += rv * gate_w[d];
        }
#pragma unroll
        for (int off = 16; off; off >>= 1) s += __shfl_xor_sync(0xffffffffu, s, off);
        if (lane == 0) coef[bon] = s + gate_b[0];
    }
    __syncthreads();
    {
        int bo = w;
        float acc = 0.f;
        for (int d = lane; d < 1024; d += 32) {
            float v;
            if (d < 512) {
                float mxv = -1e30f;
#pragma unroll
                for (int n = 0; n < 8; n++) {
                    int bon = bo * 8 + n;
                    float rv = (d < 256) ? g_srmax[bon * 256 + d] : g_drmax[bon * 256 + d - 256];
                    mxv = fmaxf(mxv, coef[bon] * rv);
                }
                v = mxv;
            } else {
                int dd = d - 512;
                float smv = 0.f;
#pragma unroll
                for (int n = 0; n < 8; n++) {
                    int bon = bo * 8 + n;
                    float rv = (dd < 256) ? g_srmax[bon * 256 + dd] : g_drmax[bon * 256 + dd - 256];
                    smv += coef[bon] * rv;
                }
                v = smv * 0.125f;
            }
            acc += v * out_w[d];
        }
#pragma unroll
        for (int off = 16; off; off >>= 1) acc += __shfl_xor_sync(0xffffffffu, acc, off);
        if (lane == 0) logits[bo] = acc + out_b[0];
    }
    __syncthreads();
    if (tid < 4) {
        int b = tid;
        float m = -1e30f;
        for (int o = 0; o < 4; o++) m = fmaxf(m, logits[b * 4 + o]);
        float e[4], s = 0.f;
        for (int o = 0; o < 4; o++) { e[o] = expf(logits[b * 4 + o] - m); s += e[o]; }
        for (int o = 0; o < 4; o++) out[b * 4 + o] = e[o] / s;
    }
}

// ---------------- host orchestration ----------------
#define SYM(p, s) do { void* _t = nullptr; cudaGetSymbolAddress(&_t, s); p = (float*)_t; } while (0)

static const int GRU_SMEM = (96 * WP + 8 * HP + 128 * 7) * 4;  // 111,744 B

extern "C" void kernel_launch(void* const* d_in, const int* in_sizes, int n_in,
                              void* d_out, int out_size) {
    const float* statement = (const float*)d_in[0];
    const float* answer    = (const float*)d_in[1];
    const float* refs      = (const float*)d_in[2];
    const float* ctx_wih   = (const float*)d_in[3];
    const float* ctx_whh   = (const float*)d_in[4];
    const float* ctx_bih   = (const float*)d_in[5];
    const float* ctx_bhh   = (const float*)d_in[6];
    const float* sr_wih    = (const float*)d_in[7];
    const float* sr_whh    = (const float*)d_in[8];
    const float* sr_bih    = (const float*)d_in[9];
    const float* sr_bhh    = (const float*)d_in[10];
    const float* dr_wih    = (const float*)d_in[11];
    const float* dr_whh    = (const float*)d_in[12];
    const float* dr_bih    = (const float*)d_in[13];
    const float* dr_bhh    = (const float*)d_in[14];
    const float* gate_w    = (const float*)d_in[15];
    const float* gate_b    = (const float*)d_in[16];
    const float* out_w     = (const float*)d_in[17];
    const float* out_b     = (const float*)d_in[18];
    float* out = (float*)d_out;

    float *stmt_in, *xg_stmt, *stmt_h, *xg_docs, *docs_h;
    float *hs0, *hs1, *hd0, *hd1;
    float *matchb, *p1, *p2t, *read_sum, *doc_read, *dri, *mmb, *att;
    float *xg_sr, *xg_dr, *hsr0, *hsr1, *hdr0, *hdr1, *srmax, *drmax;
    SYM(stmt_in, g_stmt_in); SYM(xg_stmt, g_xg_stmt); SYM(stmt_h, g_stmt_h);
    SYM(xg_docs, g_xg_docs); SYM(docs_h, g_docs_h);
    SYM(hs0, g_hs0); SYM(hs1, g_hs1); SYM(hd0, g_hd0); SYM(hd1, g_hd1);
    SYM(matchb, g_match); SYM(p1, g_p1); SYM(p2t, g_p2t);
    SYM(read_sum, g_read_sum); SYM(doc_read, g_doc_read); SYM(dri, g_dri);
    SYM(mmb, g_mm); SYM(att, g_att);
    SYM(xg_sr, g_xg_sr); SYM(xg_dr, g_xg_dr);
    SYM(hsr0, g_hsr0); SYM(hsr1, g_hsr1); SYM(hdr0, g_hdr0); SYM(hdr1, g_hdr1);
    SYM(srmax, g_srmax); SYM(drmax, g_drmax);

    cudaFuncSetAttribute(gru_phase, cudaFuncAttributeMaxDynamicSharedMemorySize, GRU_SMEM);

    init_state<<<128, 256>>>();
    concat_stmt<<<4096, 256>>>(statement, answer);

    // input projections for ctx GRU (TN: W is [768, in])
    gemm_tf32<1><<<dim3(6, 32, 1), 256>>>(stmt_in, ctx_wih, ctx_bih, xg_stmt,
                                          768, 256, 0, 0, 0, 1, 1);
    gemm_tf32<1><<<dim3(6, 128, 1), 256>>>(refs, ctx_wih, ctx_bih, xg_docs,
                                           768, 256, 0, 0, 0, 1, 1);

    // phase A: ctx GRU — stmt (2x8-seq lanes, T=256) || docs (16x8-seq lanes, T=128)
    {
        GG gs; gs.xg = xg_stmt; gs.whh = ctx_whh; gs.bhh = ctx_bhh;
        gs.h0 = hs0; gs.h1 = hs1; gs.ys = stmt_h; gs.hmax = nullptr;
        gs.T = 256; gs.nsg = 2; gs.slotbase = 0;
        GG gd; gd.xg = xg_docs; gd.whh = ctx_whh; gd.bhh = ctx_bhh;
        gd.h0 = hd0; gd.h1 = hd1; gd.ys = docs_h; gd.hmax = nullptr;
        gd.T = 128; gd.nsg = 16; gd.slotbase = 2;
        gru_phase<<<72, 256, GRU_SMEM>>>(gs, gd);  // (1+8) pairs x 8 chunks
    }

    // match[bon][s][l] = stmt[bo,s,:] . docs[bon,l,:]
    gemm_tf32<1><<<dim3(1, 2, 128), 256>>>(stmt_h, docs_h, nullptr, matchb,
                                           128, 256, 65536, 32768, 32768, 8, 1);
    softmax_warp128<<<4096, 256>>>(matchb, p1);
    softmax_cols_t<<<dim3(32, 128), 128>>>();
    // read_sum = p1 @ docs ; doc_read = p2t @ stmt
    gemm_tf32<0><<<dim3(2, 2, 128), 256>>>(p1, docs_h, nullptr, read_sum,
                                           256, 128, 32768, 32768, 65536, 1, 1);
    gemm_tf32<0><<<dim3(2, 1, 128), 256>>>(p2t, stmt_h, nullptr, doc_read,
                                           256, 256, 32768, 65536, 32768, 1, 8);
    concat_dri<<<4096, 256>>>();

    // doc-doc cross attention per bo: mm = dri @ dri^T ; softmax ; att = p3 @ dri
    gemm_tf32<1><<<dim3(8, 8, 16), 256>>>(dri, dri, nullptr, mmb,
                                          1024, 512, 524288, 524288, 1048576, 1, 1);
    softmax_block1024<<<16384, 256>>>(mmb, mmb);
    gemm_tf32<0><<<dim3(4, 8, 16), 256>>>(mmb, dri, nullptr, att,
                                          512, 1024, 1048576, 524288, 524288, 1, 1);

    // input projections for reasoning GRUs
    gemm_tf32<1><<<dim3(6, 256, 1), 256>>>(read_sum, sr_wih, sr_bih, xg_sr,
                                           768, 256, 0, 0, 0, 1, 1);
    gemm_tf32<1><<<dim3(6, 128, 1), 256>>>(att, dr_wih, dr_bih, xg_dr,
                                           768, 512, 0, 0, 0, 1, 1);

    // phase C: reasoning GRUs — sr (16x8-seq lanes, T=256) || dr (16x8-seq, T=128)
    {
        GG ga; ga.xg = xg_sr; ga.whh = sr_whh; ga.bhh = sr_bhh;
        ga.h0 = hsr0; ga.h1 = hsr1; ga.ys = nullptr; ga.hmax = srmax;
        ga.T = 256; ga.nsg = 16; ga.slotbase = 32;
        GG gb; gb.xg = xg_dr; gb.whh = dr_whh; gb.bhh = dr_bhh;
        gb.h0 = hdr0; gb.h1 = hdr1; gb.ys = nullptr; gb.hmax = drmax;
        gb.T = 128; gb.nsg = 16; gb.slotbase = 48;
        gru_phase<<<128, 256, GRU_SMEM>>>(ga, gb);  // (8+8) pairs x 8 chunks
    }

    final_kernel<<<1, 512>>>(gate_w, gate_b, out_w, out_b, out);
}

// round 12
// speedup vs baseline: 1.4425x; 1.4425x over previous
#include <cuda_runtime.h>
#include <math.h>

// Problem dims: B=4 O=4 L=128 N=8 V=256 H=256, Ls=2L=256, BO=16, BON=128, NL=1024

// ---------------- scratch (device globals; no allocation allowed) ----------------
__device__ float g_stmt_in[16 * 256 * 256];
__device__ float g_xg_stmt[16 * 256 * 768];
__device__ float g_stmt_h[16 * 256 * 256];
__device__ float g_xg_docs[128 * 128 * 768];
__device__ float g_docs_h[128 * 128 * 256];
__device__ float g_hs0[16 * 256], g_hs1[16 * 256];
__device__ float g_hd0[128 * 256], g_hd1[128 * 256];
__device__ float g_match[128 * 256 * 128];
__device__ float g_p1[128 * 256 * 128];
__device__ float g_p2t[128 * 128 * 256];
__device__ float g_read_sum[128 * 256 * 256];
__device__ float g_doc_read[128 * 128 * 256];
__device__ float g_dri[128 * 128 * 512];
__device__ float g_mm[16 * 1024 * 1024];
__device__ float g_att[128 * 128 * 512];
__device__ float g_xg_sr[128 * 256 * 768];
__device__ float g_xg_dr[128 * 128 * 768];
__device__ float g_hsr0[128 * 256], g_hsr1[128 * 256];
__device__ float g_hdr0[128 * 256], g_hdr1[128 * 256];
__device__ float g_srmax[128 * 256], g_drmax[128 * 256];

// per-(slot, chunk) monotonic step flags: 64 slots x 8 chunks, 128B stride
__device__ unsigned g_flag[64 * 8 * 32];

// ---------------- init ----------------
__global__ void init_state() {
    int i = blockIdx.x * 256 + threadIdx.x;  // 32768 threads
    if (i < 64 * 8 * 32) g_flag[i] = 0u;
    if (i < 16 * 256) { g_hs0[i] = 0.f; g_hs1[i] = 0.f; }
    if (i < 128 * 256) {
        g_hd0[i] = 0.f;  g_hd1[i] = 0.f;
        g_hsr0[i] = 0.f; g_hsr1[i] = 0.f;
        g_hdr0[i] = 0.f; g_hdr1[i] = 0.f;
    }
}

// ---------------- build stmt = cat(question, answer) ----------------
__global__ void concat_stmt(const float* __restrict__ statement,
                            const float* __restrict__ answer) {
    int idx = blockIdx.x * 256 + threadIdx.x;  // 1048576
    int v = idx & 255;
    int s = (idx >> 8) & 255;
    int bo = idx >> 16;
    int b = bo >> 2;
    float val;
    if (s < 128) val = statement[(b * 128 + s) * 256 + v];
    else         val = answer[(bo * 128 + (s - 128)) * 256 + v];
    g_stmt_in[idx] = val;
}

// ---------------- dri = cat(docs, doc_read) ----------------
__global__ void concat_dri() {
    for (int idx = blockIdx.x * blockDim.x + threadIdx.x; idx < 128 * 128 * 512;
         idx += gridDim.x * blockDim.x) {
        int h = idx & 511;
        int rest = idx >> 9;
        g_dri[idx] = (h < 256) ? g_docs_h[rest * 256 + h]
                               : g_doc_read[rest * 256 + (h - 256)];
    }
}

// ---------------- tf32 tensor-core GEMM ----------------
__device__ __forceinline__ unsigned f2tf(float x) {
    unsigned r;
    asm("cvt.rna.tf32.f32 %0, %1;" : "=r"(r) : "f"(x));
    return r;
}

__device__ __forceinline__ void mma_tf32(float4& d, const unsigned* a, const unsigned* b) {
    asm volatile(
        "mma.sync.aligned.m16n8k8.row.col.f32.tf32.tf32.f32 "
        "{%0,%1,%2,%3}, {%4,%5,%6,%7}, {%8,%9}, {%0,%1,%2,%3};"
        : "+f"(d.x), "+f"(d.y), "+f"(d.z), "+f"(d.w)
        : "r"(a[0]), "r"(a[1]), "r"(a[2]), "r"(a[3]), "r"(b[0]), "r"(b[1]));
}

// Tile 128x128, K-tile 32, 256 threads (8 warps, each 64x32).
// TB=1: C = A[M,K] * B[N,K]^T (+bias);  TB=0: C = A[M,K] * B[K,N] (+bias)
template <int TB>
__global__ void __launch_bounds__(256) gemm_tf32(
    const float* __restrict__ A, const float* __restrict__ B,
    const float* __restrict__ bias, float* __restrict__ C,
    int N, int K, long long sA, long long sB, long long sC,
    int divA, int divB) {
    const int tid = threadIdx.x;
    int z = blockIdx.z;
    A += (long long)(z / divA) * sA + (long long)(blockIdx.y * 128) * K;
    if (TB) B += (long long)(z / divB) * sB + (long long)(blockIdx.x * 128) * K;
    else    B += (long long)(z / divB) * sB + blockIdx.x * 128;
    C += (long long)z * sC + (long long)(blockIdx.y * 128) * N + blockIdx.x * 128;

    __shared__ unsigned As[128 * 36];   // [m][k], pitch 36 -> conflict-free frags
    __shared__ unsigned Bs[128 * 36];   // TN: [n][k] pitch 36; NN: [k][n] pitch 132

    const int warp = tid >> 5, lane = tid & 31;
    const int wm = (warp & 1) * 64, wn = (warp >> 1) * 32;
    const int lq = lane >> 2, lr = lane & 3;

    const int sm = tid >> 3;         // 0..31 (row group, +32*i)
    const int sk = (tid & 7) * 4;    // 0..28
    const int bk = tid >> 5;         // 0..7 (NN k row, +8*i)
    const int bn = (tid & 31) * 4;   // 0..124

    float4 acc[4][4];
#pragma unroll
    for (int i = 0; i < 4; i++)
#pragma unroll
        for (int j = 0; j < 4; j++) acc[i][j] = make_float4(0.f, 0.f, 0.f, 0.f);

    float4 pa[4], pb[4];
#pragma unroll
    for (int i = 0; i < 4; i++)
        pa[i] = *reinterpret_cast<const float4*>(&A[(long long)(sm + 32 * i) * K + sk]);
    if (TB) {
#pragma unroll
        for (int i = 0; i < 4; i++)
            pb[i] = *reinterpret_cast<const float4*>(&B[(long long)(sm + 32 * i) * K + sk]);
    } else {
#pragma unroll
        for (int i = 0; i < 4; i++)
            pb[i] = *reinterpret_cast<const float4*>(&B[(long long)(bk + 8 * i) * N + bn]);
    }

    int k0 = 0;
    for (;;) {
#pragma unroll
        for (int i = 0; i < 4; i++) {
            uint4 u;
            u.x = f2tf(pa[i].x); u.y = f2tf(pa[i].y); u.z = f2tf(pa[i].z); u.w = f2tf(pa[i].w);
            *reinterpret_cast<uint4*>(&As[(sm + 32 * i) * 36 + sk]) = u;
        }
#pragma unroll
        for (int i = 0; i < 4; i++) {
            uint4 u;
            u.x = f2tf(pb[i].x); u.y = f2tf(pb[i].y); u.z = f2tf(pb[i].z); u.w = f2tf(pb[i].w);
            if (TB) *reinterpret_cast<uint4*>(&Bs[(sm + 32 * i) * 36 + sk]) = u;
            else    *reinterpret_cast<uint4*>(&Bs[(bk + 8 * i) * 132 + bn]) = u;
        }
        __syncthreads();

        int k1 = k0 + 32;
        if (k1 < K) {
#pragma unroll
            for (int i = 0; i < 4; i++)
                pa[i] = *reinterpret_cast<const float4*>(&A[(long long)(sm + 32 * i) * K + k1 + sk]);
            if (TB) {
#pragma unroll
                for (int i = 0; i < 4; i++)
                    pb[i] = *reinterpret_cast<const float4*>(&B[(long long)(sm + 32 * i) * K + k1 + sk]);
            } else {
#pragma unroll
                for (int i = 0; i < 4; i++)
                    pb[i] = *reinterpret_cast<const float4*>(&B[(long long)(k1 + bk + 8 * i) * N + bn]);
            }
        }

#pragma unroll
        for (int kk = 0; kk < 32; kk += 8) {
            unsigned a[4][4];
#pragma unroll
            for (int mt = 0; mt < 4; mt++) {
                int r = (wm + mt * 16 + lq) * 36 + kk + lr;
                a[mt][0] = As[r];
                a[mt][1] = As[r + 8 * 36];
                a[mt][2] = As[r + 4];
                a[mt][3] = As[r + 8 * 36 + 4];
            }
            unsigned b[4][2];
#pragma unroll
            for (int nt = 0; nt < 4; nt++) {
                if (TB) {
                    int r = (wn + nt * 8 + lq) * 36 + kk + lr;
                    b[nt][0] = Bs[r];
                    b[nt][1] = Bs[r + 4];
                } else {
                    int r = (kk + lr) * 132 + wn + nt * 8 + lq;
                    b[nt][0] = Bs[r];
                    b[nt][1] = Bs[r + 4 * 132];
                }
            }
#pragma unroll
            for (int mt = 0; mt < 4; mt++)
#pragma unroll
                for (int nt = 0; nt < 4; nt++) mma_tf32(acc[mt][nt], a[mt], b[nt]);
        }
        if (k1 >= K) break;
        __syncthreads();
        k0 = k1;
    }

#pragma unroll
    for (int nt = 0; nt < 4; nt++) {
        int col = wn + nt * 8 + 2 * lr;
        float bx = 0.f, by = 0.f;
        if (bias) {
            int cg = blockIdx.x * 128 + col;
            bx = bias[cg]; by = bias[cg + 1];
        }
#pragma unroll
        for (int mt = 0; mt < 4; mt++) {
            int row = wm + mt * 16 + lq;
            float4 v = acc[mt][nt];
            float2 v0 = make_float2(v.x + bx, v.y + by);
            float2 v1 = make_float2(v.z + bx, v.w + by);
            *reinterpret_cast<float2*>(&C[(long long)row * N + col]) = v0;
            *reinterpret_cast<float2*>(&C[(long long)(row + 8) * N + col]) = v1;
        }
    }
}

// ---------------- softmax: 1024 cols, block per row, regs-resident ----------------
__global__ void __launch_bounds__(256) softmax_block1024(const float* __restrict__ in,
                                                         float* __restrict__ out) {
    long long row = blockIdx.x;
    const float4* x = reinterpret_cast<const float4*>(in + row * 1024);
    float4* y = reinterpret_cast<float4*>(out + row * 1024);
    int tid = threadIdx.x, warp = tid >> 5, lane = tid & 31;
    __shared__ float redm[8], reds[8];
    float4 v = x[tid];
    float m = fmaxf(fmaxf(v.x, v.y), fmaxf(v.z, v.w));
#pragma unroll
    for (int off = 16; off; off >>= 1) m = fmaxf(m, __shfl_xor_sync(0xffffffffu, m, off));
    if (lane == 0) redm[warp] = m;
    __syncthreads();
    m = redm[0];
#pragma unroll
    for (int i = 1; i < 8; i++) m = fmaxf(m, redm[i]);
    v.x = __expf(v.x - m); v.y = __expf(v.y - m); v.z = __expf(v.z - m); v.w = __expf(v.w - m);
    float s = v.x + v.y + v.z + v.w;
#pragma unroll
    for (int off = 16; off; off >>= 1) s += __shfl_xor_sync(0xffffffffu, s, off);
    if (lane == 0) reds[warp] = s;
    __syncthreads();
    s = reds[0];
#pragma unroll
    for (int i = 1; i < 8; i++) s += reds[i];
    float inv = 1.f / s;
    v.x *= inv; v.y *= inv; v.z *= inv; v.w *= inv;
    y[tid] = v;
}

// ---------------- softmax: 128 cols, warp per row (8 rows per block) ----------------
__global__ void __launch_bounds__(256) softmax_warp128(const float* __restrict__ in,
                                                       float* __restrict__ out) {
    int warp = threadIdx.x >> 5, lane = threadIdx.x & 31;
    long long row = (long long)blockIdx.x * 8 + warp;
    const float4* x = reinterpret_cast<const float4*>(in + row * 128);
    float4* y = reinterpret_cast<float4*>(out + row * 128);
    float4 v = x[lane];
    float m = fmaxf(fmaxf(v.x, v.y), fmaxf(v.z, v.w));
#pragma unroll
    for (int off = 16; off; off >>= 1) m = fmaxf(m, __shfl_xor_sync(0xffffffffu, m, off));
    v.x = __expf(v.x - m); v.y = __expf(v.y - m); v.z = __expf(v.z - m); v.w = __expf(v.w - m);
    float s = v.x + v.y + v.z + v.w;
#pragma unroll
    for (int off = 16; off; off >>= 1) s += __shfl_xor_sync(0xffffffffu, s, off);
    float inv = 1.f / s;
    v.x *= inv; v.y *= inv; v.z *= inv; v.w *= inv;
    y[lane] = v;
}

// ---------------- column softmax of match over s, output transposed [bon][l][s] ----------------
__global__ void __launch_bounds__(128) softmax_cols_t() {
    int bon = blockIdx.y;
    int l = blockIdx.x * 4 + (threadIdx.x >> 5);
    int lane = threadIdx.x & 31;
    const float* base = g_match + (long long)bon * 256 * 128 + l;
    float v[8];
    float m = -1e30f;
#pragma unroll
    for (int i = 0; i < 8; i++) {
        v[i] = base[(lane + 32 * i) * 128];
        m = fmaxf(m, v[i]);
    }
#pragma unroll
    for (int off = 16; off; off >>= 1) m = fmaxf(m, __shfl_xor_sync(0xffffffffu, m, off));
    float sum = 0.f;
#pragma unroll
    for (int i = 0; i < 8; i++) { v[i] = __expf(v[i] - m); sum += v[i]; }
#pragma unroll
    for (int off = 16; off; off >>= 1) sum += __shfl_xor_sync(0xffffffffu, sum, off);
    float inv = 1.f / sum;
    float* o = g_p2t + ((long long)bon * 128 + l) * 256;
#pragma unroll
    for (int i = 0; i < 8; i++) o[lane + 32 * i] = v[i] * inv;
}

// ---------------- acquire/relaxed flag ops ----------------
__device__ __forceinline__ unsigned ld_acq(const unsigned* p) {
    unsigned v;
    asm volatile("ld.global.acquire.gpu.u32 %0, [%1];" : "=r"(v) : "l"(p) : "memory");
    return v;
}
__device__ __forceinline__ void st_rlx(unsigned* p, unsigned v) {
    asm volatile("st.global.relaxed.gpu.u32 [%0], %1;" :: "l"(p), "r"(v) : "memory");
}

// ---------------- persistent fused GRU phase ----------------
struct GG {
    const float* xg;    // [nseq][T][768]
    const float* whh;   // [768][256]
    const float* bhh;   // [768]
    float* h0;          // [nseq][256] (t even input)
    float* h1;
    float* ys;          // optional [nseq][T][256]
    float* hmax;        // optional [nseq][256]
    int T;
    int nsg;            // seq groups of 16
    int slotbase;       // flag slot base (one slot per sgrp)
};

#define WP 260  // weight row pitch (floats) -> conflict-free 8-row 16B frags
#define HP 260  // h row pitch

// packed fp32x2 FMA (sm_10x): acc{lo,hi} += a{lo,hi} * b{lo,hi}
#define FMA2(acc, a, b) \
    asm("fma.rn.f32x2 %0, %1, %2, %0;" : "+l"(acc) : "l"(a), "l"(b))
#define UNPK(lo, hi, v) \
    asm("mov.b64 {%0,%1}, %2;" : "=f"(lo), "=f"(hi) : "l"(v))

__device__ __forceinline__ float red2(unsigned long long a, unsigned long long b) {
    float l0, h0, l1, h1;
    UNPK(l0, h0, a); UNPK(l1, h1, b);
    return (l0 + h0) + (l1 + h1);
}

// block = 256 threads (8 warps), tile = 16 seqs x 32 cols (one col chunk).
// col-warp cw = warp&3 owns 8 cols; k-warp kw = warp>>2 handles half the k range.
// lane: c8 = lane&7 (col within 8), sq = lane>>3; thread cells = (col, seqs sq+4j).
// Cross-kw partial sums merged through smem once per step.
// Sync protocol per step: the kw0 half (tid<128) does gate math + h stores, then a
// kw0-only named barrier, then tid 0 fences + publishes the step flag; MEANWHILE
// the kw1 half's threads 128-135 poll the 8 group flags for the NEXT step. The
// top-of-loop __syncthreads joins both halves (poll overlapped with gate math).
__global__ void __launch_bounds__(256) gru_phase(GG ga, GG gb) {
    extern __shared__ float sm[];
    float* ws = sm;                         // 96 x WP
    float* hs = sm + 96 * WP;               // 16 x HP
    float* red = sm + 96 * WP + 16 * HP;    // 128 x 13 (pad-13: conflict-free)

    GG g;
    int sgrp, mychunk;
    {
        int b = blockIdx.x;
        int blocks0 = ga.nsg * 8;
        if (b < blocks0) { g = ga; sgrp = b >> 3; mychunk = b & 7; }
        else { g = gb; int bb = b - blocks0; sgrp = bb >> 3; mychunk = bb & 7; }
    }
    const int colbase = mychunk * 32;
    unsigned* flags = &g_flag[(g.slotbase + sgrp) * 8 * 32];
    const int tid = threadIdx.x;
    const int warp = tid >> 5, lane = tid & 31;
    const int kw = warp >> 2, cw = warp & 3;
    const int c8 = lane & 7, sq = lane >> 3;
    const int widx = cw * 8 + c8;   // col within chunk, 0..31
    const int col = colbase + widx;

    // load weight slice: ws row r = gate*32 + j holds whh[gate*256 + colbase + j][:]
    for (int i = tid; i < 96 * 64; i += 256) {
        int r = i >> 6, q = i & 63;
        float4 v = __ldg(reinterpret_cast<const float4*>(
            &g.whh[(long long)((r >> 5) * 256 + colbase + (r & 31)) * 256 + q * 4]));
        *reinterpret_cast<float4*>(&ws[r * WP + q * 4]) = v;
    }
    const float br = g.bhh[col], bz = g.bhh[256 + col], bn = g.bhh[512 + col];
    float mx[4] = {-1e30f, -1e30f, -1e30f, -1e30f};

    const ulonglong2* wR = reinterpret_cast<const ulonglong2*>(&ws[(0  + widx) * WP]);
    const ulonglong2* wZ = reinterpret_cast<const ulonglong2*>(&ws[(32 + widx) * WP]);
    const ulonglong2* wN = reinterpret_cast<const ulonglong2*>(&ws[(64 + widx) * WP]);
    const ulonglong2* hr_[4];
#pragma unroll
    for (int j = 0; j < 4; j++)
        hr_[j] = reinterpret_cast<const ulonglong2*>(&hs[(sq + 4 * j) * HP]);

    const int q0 = kw * 32, q1 = q0 + 32;   // half of the 64 ulonglong2 k-units
    const int T = g.T;

    for (int t = 0; t < T; t++) {
        // join: prev step's publish done (kw0) and polls confirmed (kw1); hs free
        __syncthreads();
        const float* hin = (t & 1) ? g.h1 : g.h0;
        float* hout = (t & 1) ? g.h0 : g.h1;
        const float4* tb = reinterpret_cast<const float4*>(hin + (long long)sgrp * 16 * 256);
        // stage h tile [16][256]: 1024 float4 over 256 threads
#pragma unroll
        for (int i = 0; i < 4; i++) {
            int idx = tid + i * 256;  // seq = idx>>6, unit = idx&63
            float4 v = __ldcg(tb + idx);
            *reinterpret_cast<float4*>(&hs[(idx >> 6) * HP + (idx & 63) * 4]) = v;
        }
        // xg prefetch (only kw==0 threads consume)
        float xr[4], xz[4], xn[4];
        if (kw == 0) {
#pragma unroll
            for (int j = 0; j < 4; j++) {
                long long base = ((long long)(sgrp * 16 + sq + 4 * j) * T + t) * 768;
                xr[j] = __ldg(&g.xg[base + col]);
                xz[j] = __ldg(&g.xg[base + 256 + col]);
                xn[j] = __ldg(&g.xg[base + 512 + col]);
            }
        }
        __syncthreads();  // hs staged

        unsigned long long aR[4][2], aZ[4][2], aN[4][2];
#pragma unroll
        for (int j = 0; j < 4; j++) {
            aR[j][0] = aR[j][1] = 0ull;
            aZ[j][0] = aZ[j][1] = 0ull;
            aN[j][0] = aN[j][1] = 0ull;
        }
#pragma unroll 4
        for (int q = q0; q < q1; q++) {
            ulonglong2 r_ = wR[q], z_ = wZ[q], n_ = wN[q];
#pragma unroll
            for (int j = 0; j < 4; j++) {
                ulonglong2 h = hr_[j][q];
                FMA2(aR[j][0], r_.x, h.x); FMA2(aR[j][1], r_.y, h.y);
                FMA2(aZ[j][0], z_.x, h.x); FMA2(aZ[j][1], z_.y, h.y);
                FMA2(aN[j][0], n_.x, h.x); FMA2(aN[j][1], n_.y, h.y);
            }
        }
        float pr[4], pz[4], pn[4];
#pragma unroll
        for (int j = 0; j < 4; j++) {
            pr[j] = red2(aR[j][0], aR[j][1]);
            pz[j] = red2(aZ[j][0], aZ[j][1]);
            pn[j] = red2(aN[j][0], aN[j][1]);
        }
        // merge kw halves through smem
        if (kw == 1) {
            float* rp = &red[(tid - 128) * 13];
#pragma unroll
            for (int j = 0; j < 4; j++) {
                rp[j] = pr[j]; rp[4 + j] = pz[j]; rp[8 + j] = pn[j];
            }
        }
        __syncthreads();  // partials visible
        if (kw == 0) {
            const float* rp = &red[tid * 13];
#pragma unroll
            for (int j = 0; j < 4; j++) {
                int sl = sq + 4 * j;
                long long seq = sgrp * 16 + sl;
                float hrv = pr[j] + rp[j] + br;
                float hzv = pz[j] + rp[4 + j] + bz;
                float hnv = pn[j] + rp[8 + j] + bn;
                float r = 1.f / (1.f + expf(-(xr[j] + hrv)));
                float z = 1.f / (1.f + expf(-(xz[j] + hzv)));
                float n = tanhf(xn[j] + r * hnv);
                float hold = hs[sl * HP + col];
                float h = (1.f - z) * n + z * hold;
                hout[seq * 256 + col] = h;
                if (g.ys) g.ys[(seq * T + t) * 256 + col] = h;
                mx[j] = fmaxf(mx[j], h);
            }
            // kw0-only barrier: all h stores of this block observed, then publish
            asm volatile("bar.sync 1, 128;" ::: "memory");
            if (tid == 0 && t + 1 < T) {
                __threadfence();                       // cumulative: orders kw0 stores
                st_rlx(&flags[mychunk * 32], (unsigned)(t + 1));
            }
        } else {
            // kw1: poll next step's flags concurrently with kw0's gate math
            if (t + 1 < T && tid < 136) {
                while (ld_acq(&flags[(tid - 128) * 32]) < (unsigned)(t + 1)) {}
            }
        }
    }
    if (g.hmax && kw == 0) {
#pragma unroll
        for (int j = 0; j < 4; j++) {
            long long seq = sgrp * 16 + sq + 4 * j;
            g.hmax[seq * 256 + col] = mx[j];
        }
    }
}

// ---------------- final: coef gate, feat, output head, softmax over options ----------------
__global__ void __launch_bounds__(512) final_kernel(
    const float* __restrict__ gate_w, const float* __restrict__ gate_b,
    const float* __restrict__ out_w, const float* __restrict__ out_b,
    float* __restrict__ out) {
    __shared__ float coef[128];
    __shared__ float logits[16];
    int tid = threadIdx.x, w = tid >> 5, lane = tid & 31;
    for (int bon = w; bon < 128; bon += 16) {
        float s = 0.f;
        for (int d = lane; d < 512; d += 32) {
            float rv = (d < 256) ? g_srmax[bon * 256 + d] : g_drmax[bon * 256 + d - 256];
            s += rv * gate_w[d];
        }
#pragma unroll
        for (int off = 16; off; off >>= 1) s += __shfl_xor_sync(0xffffffffu, s, off);
        if (lane == 0) coef[bon] = s + gate_b[0];
    }
    __syncthreads();
    {
        int bo = w;
        float acc = 0.f;
        for (int d = lane; d < 1024; d += 32) {
            float v;
            if (d < 512) {
                float mxv = -1e30f;
#pragma unroll
                for (int n = 0; n < 8; n++) {
                    int bon = bo * 8 + n;
                    float rv = (d < 256) ? g_srmax[bon * 256 + d] : g_drmax[bon * 256 + d - 256];
                    mxv = fmaxf(mxv, coef[bon] * rv);
                }
                v = mxv;
            } else {
                int dd = d - 512;
                float smv = 0.f;
#pragma unroll
                for (int n = 0; n < 8; n++) {
                    int bon = bo * 8 + n;
                    float rv = (dd < 256) ? g_srmax[bon * 256 + dd] : g_drmax[bon * 256 + dd - 256];
                    smv += coef[bon] * rv;
                }
                v = smv * 0.125f;
            }
            acc += v * out_w[d];
        }
#pragma unroll
        for (int off = 16; off; off >>= 1) acc += __shfl_xor_sync(0xffffffffu, acc, off);
        if (lane == 0) logits[bo] = acc + out_b[0];
    }
    __syncthreads();
    if (tid < 4) {
        int b = tid;
        float m = -1e30f;
        for (int o = 0; o < 4; o++) m = fmaxf(m, logits[b * 4 + o]);
        float e[4], s = 0.f;
        for (int o = 0; o < 4; o++) { e[o] = expf(logits[b * 4 + o] - m); s += e[o]; }
        for (int o = 0; o < 4; o++) out[b * 4 + o] = e[o] / s;
    }
}

// ---------------- host orchestration ----------------
#define SYM(p, s) do { void* _t = nullptr; cudaGetSymbolAddress(&_t, s); p = (float*)_t; } while (0)

static const int GRU_SMEM = (96 * WP + 16 * HP + 128 * 13) * 4;  // 123,136 B

extern "C" void kernel_launch(void* const* d_in, const int* in_sizes, int n_in,
                              void* d_out, int out_size) {
    const float* statement = (const float*)d_in[0];
    const float* answer    = (const float*)d_in[1];
    const float* refs      = (const float*)d_in[2];
    const float* ctx_wih   = (const float*)d_in[3];
    const float* ctx_whh   = (const float*)d_in[4];
    const float* ctx_bih   = (const float*)d_in[5];
    const float* ctx_bhh   = (const float*)d_in[6];
    const float* sr_wih    = (const float*)d_in[7];
    const float* sr_whh    = (const float*)d_in[8];
    const float* sr_bih    = (const float*)d_in[9];
    const float* sr_bhh    = (const float*)d_in[10];
    const float* dr_wih    = (const float*)d_in[11];
    const float* dr_whh    = (const float*)d_in[12];
    const float* dr_bih    = (const float*)d_in[13];
    const float* dr_bhh    = (const float*)d_in[14];
    const float* gate_w    = (const float*)d_in[15];
    const float* gate_b    = (const float*)d_in[16];
    const float* out_w     = (const float*)d_in[17];
    const float* out_b     = (const float*)d_in[18];
    float* out = (float*)d_out;

    float *stmt_in, *xg_stmt, *stmt_h, *xg_docs, *docs_h;
    float *hs0, *hs1, *hd0, *hd1;
    float *matchb, *p1, *p2t, *read_sum, *doc_read, *dri, *mmb, *att;
    float *xg_sr, *xg_dr, *hsr0, *hsr1, *hdr0, *hdr1, *srmax, *drmax;
    SYM(stmt_in, g_stmt_in); SYM(xg_stmt, g_xg_stmt); SYM(stmt_h, g_stmt_h);
    SYM(xg_docs, g_xg_docs); SYM(docs_h, g_docs_h);
    SYM(hs0, g_hs0); SYM(hs1, g_hs1); SYM(hd0, g_hd0); SYM(hd1, g_hd1);
    SYM(matchb, g_match); SYM(p1, g_p1); SYM(p2t, g_p2t);
    SYM(read_sum, g_read_sum); SYM(doc_read, g_doc_read); SYM(dri, g_dri);
    SYM(mmb, g_mm); SYM(att, g_att);
    SYM(xg_sr, g_xg_sr); SYM(xg_dr, g_xg_dr);
    SYM(hsr0, g_hsr0); SYM(hsr1, g_hsr1); SYM(hdr0, g_hdr0); SYM(hdr1, g_hdr1);
    SYM(srmax, g_srmax); SYM(drmax, g_drmax);

    cudaFuncSetAttribute(gru_phase, cudaFuncAttributeMaxDynamicSharedMemorySize, GRU_SMEM);

    init_state<<<128, 256>>>();
    concat_stmt<<<4096, 256>>>(statement, answer);

    // input projections for ctx GRU (TN: W is [768, in])
    gemm_tf32<1><<<dim3(6, 32, 1), 256>>>(stmt_in, ctx_wih, ctx_bih, xg_stmt,
                                          768, 256, 0, 0, 0, 1, 1);
    gemm_tf32<1><<<dim3(6, 128, 1), 256>>>(refs, ctx_wih, ctx_bih, xg_docs,
                                           768, 256, 0, 0, 0, 1, 1);

    // phase A: ctx GRU — stmt (16 seqs, T=256) || docs (128 seqs, T=128)
    {
        GG gs; gs.xg = xg_stmt; gs.whh = ctx_whh; gs.bhh = ctx_bhh;
        gs.h0 = hs0; gs.h1 = hs1; gs.ys = stmt_h; gs.hmax = nullptr;
        gs.T = 256; gs.nsg = 1; gs.slotbase = 0;
        GG gd; gd.xg = xg_docs; gd.whh = ctx_whh; gd.bhh = ctx_bhh;
        gd.h0 = hd0; gd.h1 = hd1; gd.ys = docs_h; gd.hmax = nullptr;
        gd.T = 128; gd.nsg = 8; gd.slotbase = 8;
        gru_phase<<<72, 256, GRU_SMEM>>>(gs, gd);  // 72 blocks, 1/SM
    }

    // match[bon][s][l] = stmt[bo,s,:] . docs[bon,l,:]
    gemm_tf32<1><<<dim3(1, 2, 128), 256>>>(stmt_h, docs_h, nullptr, matchb,
                                           128, 256, 65536, 32768, 32768, 8, 1);
    softmax_warp128<<<4096, 256>>>(matchb, p1);
    softmax_cols_t<<<dim3(32, 128), 128>>>();
    // read_sum = p1 @ docs ; doc_read = p2t @ stmt
    gemm_tf32<0><<<dim3(2, 2, 128), 256>>>(p1, docs_h, nullptr, read_sum,
                                           256, 128, 32768, 32768, 65536, 1, 1);
    gemm_tf32<0><<<dim3(2, 1, 128), 256>>>(p2t, stmt_h, nullptr, doc_read,
                                           256, 256, 32768, 65536, 32768, 1, 8);
    concat_dri<<<4096, 256>>>();

    // doc-doc cross attention per bo: mm = dri @ dri^T ; softmax ; att = p3 @ dri
    gemm_tf32<1><<<dim3(8, 8, 16), 256>>>(dri, dri, nullptr, mmb,
                                          1024, 512, 524288, 524288, 1048576, 1, 1);
    softmax_block1024<<<16384, 256>>>(mmb, mmb);
    gemm_tf32<0><<<dim3(4, 8, 16), 256>>>(mmb, dri, nullptr, att,
                                          512, 1024, 1048576, 524288, 524288, 1, 1);

    // input projections for reasoning GRUs
    gemm_tf32<1><<<dim3(6, 256, 1), 256>>>(read_sum, sr_wih, sr_bih, xg_sr,
                                           768, 256, 0, 0, 0, 1, 1);
    gemm_tf32<1><<<dim3(6, 128, 1), 256>>>(att, dr_wih, dr_bih, xg_dr,
                                           768, 512, 0, 0, 0, 1, 1);

    // phase C: reasoning GRUs — sr (128 seqs, T=256) || dr (128 seqs, T=128)
    {
        GG ga; ga.xg = xg_sr; ga.whh = sr_whh; ga.bhh = sr_bhh;
        ga.h0 = hsr0; ga.h1 = hsr1; ga.ys = nullptr; ga.hmax = srmax;
        ga.T = 256; ga.nsg = 8; ga.slotbase = 32;
        GG gb; gb.xg = xg_dr; gb.whh = dr_whh; gb.bhh = dr_bhh;
        gb.h0 = hdr0; gb.h1 = hdr1; gb.ys = nullptr; gb.hmax = drmax;
        gb.T = 128; gb.nsg = 8; gb.slotbase = 48;
        gru_phase<<<128, 256, GRU_SMEM>>>(ga, gb);  // 128 blocks, 1/SM
    }

    final_kernel<<<1, 512>>>(gate_w, gate_b, out_w, out_b, out);
}

// round 13
// speedup vs baseline: 1.5475x; 1.0728x over previous
#include <cuda_runtime.h>
#include <math.h>

// Problem dims: B=4 O=4 L=128 N=8 V=256 H=256, Ls=2L=256, BO=16, BON=128, NL=1024

// ---------------- scratch (device globals; no allocation allowed) ----------------
__device__ float g_stmt_in[16 * 256 * 256];
__device__ float g_xg_stmt[16 * 256 * 768];
__device__ float g_stmt_h[16 * 256 * 256];
__device__ float g_xg_docs[128 * 128 * 768];
__device__ float g_hs0[16 * 256], g_hs1[16 * 256];
__device__ float g_hd0[128 * 256], g_hd1[128 * 256];
__device__ float g_match[128 * 256 * 128];
__device__ float g_p1[128 * 256 * 128];
__device__ float g_p2t[128 * 128 * 256];
__device__ float g_read_sum[128 * 256 * 256];
__device__ float g_dri[128 * 128 * 512];
__device__ float g_mm[16 * 1024 * 1024];
__device__ float g_att[128 * 128 * 512];
__device__ float g_xg_sr[128 * 256 * 768];
__device__ float g_xg_dr[128 * 128 * 768];
__device__ float g_hsr0[128 * 256], g_hsr1[128 * 256];
__device__ float g_hdr0[128 * 256], g_hdr1[128 * 256];
__device__ float g_srmax[128 * 256], g_drmax[128 * 256];

// per-(slot, chunk) monotonic step flags: 64 slots x 8 chunks, 128B stride
__device__ unsigned g_flag[64 * 8 * 32];

// ---------------- init ----------------
__global__ void init_state() {
    int i = blockIdx.x * 256 + threadIdx.x;  // 32768 threads
    if (i < 64 * 8 * 32) g_flag[i] = 0u;
    if (i < 16 * 256) { g_hs0[i] = 0.f; g_hs1[i] = 0.f; }
    if (i < 128 * 256) {
        g_hd0[i] = 0.f;  g_hd1[i] = 0.f;
        g_hsr0[i] = 0.f; g_hsr1[i] = 0.f;
        g_hdr0[i] = 0.f; g_hdr1[i] = 0.f;
    }
}

// ---------------- build stmt = cat(question, answer) ----------------
__global__ void concat_stmt(const float* __restrict__ statement,
                            const float* __restrict__ answer) {
    int idx = blockIdx.x * 256 + threadIdx.x;  // 1048576
    int v = idx & 255;
    int s = (idx >> 8) & 255;
    int bo = idx >> 16;
    int b = bo >> 2;
    float val;
    if (s < 128) val = statement[(b * 128 + s) * 256 + v];
    else         val = answer[(bo * 128 + (s - 128)) * 256 + v];
    g_stmt_in[idx] = val;
}

// ---------------- cp.async helpers ----------------
__device__ __forceinline__ unsigned smem_u32(const void* p) {
    return (unsigned)__cvta_generic_to_shared(p);
}
__device__ __forceinline__ void cp16(unsigned dst, const void* src) {
    asm volatile("cp.async.cg.shared.global [%0], [%1], 16;" :: "r"(dst), "l"(src));
}
template <int n> __device__ __forceinline__ void cp_wait() {
    asm volatile("cp.async.wait_group %0;" :: "n"(n) : "memory");
}

__device__ __forceinline__ void mma_tf32(float4& d, const unsigned* a, const unsigned* b) {
    asm volatile(
        "mma.sync.aligned.m16n8k8.row.col.f32.tf32.tf32.f32 "
        "{%0,%1,%2,%3}, {%4,%5,%6,%7}, {%8,%9}, {%0,%1,%2,%3};"
        : "+f"(d.x), "+f"(d.y), "+f"(d.z), "+f"(d.w)
        : "r"(a[0]), "r"(a[1]), "r"(a[2]), "r"(a[3]), "r"(b[0]), "r"(b[1]));
}

// Tile 128x128, K-tile 32, 256 threads, cp.async double-buffered, 2 blocks/SM.
// Raw fp32 bits fed to tf32 MMA (HW truncation).
// TB=1: C = A[M,K] * B[N,K]^T (+bias);  TB=0: C = A[M,K] * B[K,N] (+bias)
template <int TB>
__global__ void __launch_bounds__(256, 2) gemm_tf32(
    const float* __restrict__ A, const float* __restrict__ B,
    const float* __restrict__ bias, float* __restrict__ C,
    int N, int K, int lda, int ldb, int ldc,
    long long sA, long long sB, long long sC, int divA, int divB) {
    extern __shared__ unsigned gsm[];
    unsigned* Abuf[2] = {gsm, gsm + 4608};
    unsigned* Bbuf[2] = {gsm + 9216, gsm + 13824};

    const int tid = threadIdx.x;
    int z = blockIdx.z;
    A += (long long)(z / divA) * sA + (long long)(blockIdx.y * 128) * lda;
    if (TB) B += (long long)(z / divB) * sB + (long long)(blockIdx.x * 128) * ldb;
    else    B += (long long)(z / divB) * sB + blockIdx.x * 128;
    C += (long long)z * sC + (long long)(blockIdx.y * 128) * ldc + blockIdx.x * 128;

    const int warp = tid >> 5, lane = tid & 31;
    const int wm = (warp & 1) * 64, wn = (warp >> 1) * 32;
    const int lq = lane >> 2, lr = lane & 3;
    const int sm_ = tid >> 3;        // 0..31 (+32*i)
    const int sk = (tid & 7) * 4;    // 0..28
    const int bk = tid >> 5;         // 0..7 (+8*i)
    const int bn = (tid & 31) * 4;   // 0..124

    float4 acc[4][4];
#pragma unroll
    for (int i = 0; i < 4; i++)
#pragma unroll
        for (int j = 0; j < 4; j++) acc[i][j] = make_float4(0.f, 0.f, 0.f, 0.f);

    auto issue = [&](int s, int k0) {
        unsigned* As = Abuf[s];
        unsigned* Bs = Bbuf[s];
#pragma unroll
        for (int i = 0; i < 4; i++)
            cp16(smem_u32(&As[(sm_ + 32 * i) * 36 + sk]),
                 &A[(long long)(sm_ + 32 * i) * lda + k0 + sk]);
        if (TB) {
#pragma unroll
            for (int i = 0; i < 4; i++)
                cp16(smem_u32(&Bs[(sm_ + 32 * i) * 36 + sk]),
                     &B[(long long)(sm_ + 32 * i) * ldb + k0 + sk]);
        } else {
#pragma unroll
            for (int i = 0; i < 4; i++)
                cp16(smem_u32(&Bs[(bk + 8 * i) * 132 + bn]),
                     &B[(long long)(k0 + bk + 8 * i) * ldb + bn]);
        }
        asm volatile("cp.async.commit_group;" ::: "memory");
    };

    const int NT = K >> 5;
    issue(0, 0);
    for (int it = 0; it < NT; it++) {
        const int s = it & 1;
        if (it + 1 < NT) { issue(s ^ 1, (it + 1) * 32); cp_wait<1>(); }
        else cp_wait<0>();
        __syncthreads();
        const unsigned* As = Abuf[s];
        const unsigned* Bs = Bbuf[s];
#pragma unroll
        for (int kk = 0; kk < 32; kk += 8) {
            unsigned a[4][4];
#pragma unroll
            for (int mt = 0; mt < 4; mt++) {
                int r = (wm + mt * 16 + lq) * 36 + kk + lr;
                a[mt][0] = As[r];
                a[mt][1] = As[r + 8 * 36];
                a[mt][2] = As[r + 4];
                a[mt][3] = As[r + 8 * 36 + 4];
            }
            unsigned b[4][2];
#pragma unroll
            for (int nt = 0; nt < 4; nt++) {
                if (TB) {
                    int r = (wn + nt * 8 + lq) * 36 + kk + lr;
                    b[nt][0] = Bs[r];
                    b[nt][1] = Bs[r + 4];
                } else {
                    int r = (kk + lr) * 132 + wn + nt * 8 + lq;
                    b[nt][0] = Bs[r];
                    b[nt][1] = Bs[r + 4 * 132];
                }
            }
#pragma unroll
            for (int mt = 0; mt < 4; mt++)
#pragma unroll
                for (int nt = 0; nt < 4; nt++) mma_tf32(acc[mt][nt], a[mt], b[nt]);
        }
        __syncthreads();
    }

#pragma unroll
    for (int nt = 0; nt < 4; nt++) {
        int col = wn + nt * 8 + 2 * lr;
        float bx = 0.f, by = 0.f;
        if (bias) {
            int cg = blockIdx.x * 128 + col;
            bx = bias[cg]; by = bias[cg + 1];
        }
#pragma unroll
        for (int mt = 0; mt < 4; mt++) {
            int row = wm + mt * 16 + lq;
            float4 v = acc[mt][nt];
            float2 v0 = make_float2(v.x + bx, v.y + by);
            float2 v1 = make_float2(v.z + bx, v.w + by);
            *reinterpret_cast<float2*>(&C[(long long)row * ldc + col]) = v0;
            *reinterpret_cast<float2*>(&C[(long long)(row + 8) * ldc + col]) = v1;
        }
    }
}

// ---------------- softmax: 1024 cols, block per row, regs-resident ----------------
__global__ void __launch_bounds__(256) softmax_block1024(const float* __restrict__ in,
                                                         float* __restrict__ out) {
    long long row = blockIdx.x;
    const float4* x = reinterpret_cast<const float4*>(in + row * 1024);
    float4* y = reinterpret_cast<float4*>(out + row * 1024);
    int tid = threadIdx.x, warp = tid >> 5, lane = tid & 31;
    __shared__ float redm[8], reds[8];
    float4 v = x[tid];
    float m = fmaxf(fmaxf(v.x, v.y), fmaxf(v.z, v.w));
#pragma unroll
    for (int off = 16; off; off >>= 1) m = fmaxf(m, __shfl_xor_sync(0xffffffffu, m, off));
    if (lane == 0) redm[warp] = m;
    __syncthreads();
    m = redm[0];
#pragma unroll
    for (int i = 1; i < 8; i++) m = fmaxf(m, redm[i]);
    v.x = __expf(v.x - m); v.y = __expf(v.y - m); v.z = __expf(v.z - m); v.w = __expf(v.w - m);
    float s = v.x + v.y + v.z + v.w;
#pragma unroll
    for (int off = 16; off; off >>= 1) s += __shfl_xor_sync(0xffffffffu, s, off);
    if (lane == 0) reds[warp] = s;
    __syncthreads();
    s = reds[0];
#pragma unroll
    for (int i = 1; i < 8; i++) s += reds[i];
    float inv = 1.f / s;
    v.x *= inv; v.y *= inv; v.z *= inv; v.w *= inv;
    y[tid] = v;
}

// ---------------- softmax: 128 cols, warp per row (8 rows per block) ----------------
__global__ void __launch_bounds__(256) softmax_warp128(const float* __restrict__ in,
                                                       float* __restrict__ out) {
    int warp = threadIdx.x >> 5, lane = threadIdx.x & 31;
    long long row = (long long)blockIdx.x * 8 + warp;
    const float4* x = reinterpret_cast<const float4*>(in + row * 128);
    float4* y = reinterpret_cast<float4*>(out + row * 128);
    float4 v = x[lane];
    float m = fmaxf(fmaxf(v.x, v.y), fmaxf(v.z, v.w));
#pragma unroll
    for (int off = 16; off; off >>= 1) m = fmaxf(m, __shfl_xor_sync(0xffffffffu, m, off));
    v.x = __expf(v.x - m); v.y = __expf(v.y - m); v.z = __expf(v.z - m); v.w = __expf(v.w - m);
    float s = v.x + v.y + v.z + v.w;
#pragma unroll
    for (int off = 16; off; off >>= 1) s += __shfl_xor_sync(0xffffffffu, s, off);
    float inv = 1.f / s;
    v.x *= inv; v.y *= inv; v.z *= inv; v.w *= inv;
    y[lane] = v;
}

// ---------------- column softmax of match over s, output transposed [bon][l][s] ----------------
__global__ void __launch_bounds__(128) softmax_cols_t() {
    int bon = blockIdx.y;
    int l = blockIdx.x * 4 + (threadIdx.x >> 5);
    int lane = threadIdx.x & 31;
    const float* base = g_match + (long long)bon * 256 * 128 + l;
    float v[8];
    float m = -1e30f;
#pragma unroll
    for (int i = 0; i < 8; i++) {
        v[i] = base[(lane + 32 * i) * 128];
        m = fmaxf(m, v[i]);
    }
#pragma unroll
    for (int off = 16; off; off >>= 1) m = fmaxf(m, __shfl_xor_sync(0xffffffffu, m, off));
    float sum = 0.f;
#pragma unroll
    for (int i = 0; i < 8; i++) { v[i] = __expf(v[i] - m); sum += v[i]; }
#pragma unroll
    for (int off = 16; off; off >>= 1) sum += __shfl_xor_sync(0xffffffffu, sum, off);
    float inv = 1.f / sum;
    float* o = g_p2t + ((long long)bon * 128 + l) * 256;
#pragma unroll
    for (int i = 0; i < 8; i++) o[lane + 32 * i] = v[i] * inv;
}

// ---------------- acquire/relaxed flag ops ----------------
__device__ __forceinline__ unsigned ld_acq(const unsigned* p) {
    unsigned v;
    asm volatile("ld.global.acquire.gpu.u32 %0, [%1];" : "=r"(v) : "l"(p) : "memory");
    return v;
}
__device__ __forceinline__ void st_rlx(unsigned* p, unsigned v) {
    asm volatile("st.global.relaxed.gpu.u32 [%0], %1;" :: "l"(p), "r"(v) : "memory");
}

// ---------------- persistent fused GRU phase ----------------
struct GG {
    const float* xg;    // [nseq][T][768]
    const float* whh;   // [768][256]
    const float* bhh;   // [768]
    float* h0;          // [nseq][256] (t even input)
    float* h1;
    float* ys;          // optional [nseq][T][ysld]
    float* hmax;        // optional [nseq][256]
    int T;
    int nsg;            // seq groups of 16
    int slotbase;       // flag slot base (one slot per sgrp)
    int ysld;           // ys row pitch (floats)
};

#define WP 260  // weight row pitch (floats) -> conflict-free 8-row 16B frags
#define HP 260  // h row pitch

// packed fp32x2 FMA (sm_10x): acc{lo,hi} += a{lo,hi} * b{lo,hi}
#define FMA2(acc, a, b) \
    asm("fma.rn.f32x2 %0, %1, %2, %0;" : "+l"(acc) : "l"(a), "l"(b))
#define UNPK(lo, hi, v) \
    asm("mov.b64 {%0,%1}, %2;" : "=f"(lo), "=f"(hi) : "l"(v))

__device__ __forceinline__ float red2(unsigned long long a, unsigned long long b) {
    float l0, h0, l1, h1;
    UNPK(l0, h0, a); UNPK(l1, h1, b);
    return (l0 + h0) + (l1 + h1);
}

// block = 256 threads (8 warps), tile = 16 seqs x 32 cols (one col chunk).
// col-warp cw = warp&3 owns 8 cols; k-warp kw = warp>>2 handles half the k range.
// Sync per step: kw0 does gate math + h stores + kw0-barrier + publish; kw1
// concurrently polls next step's flags. Top-of-loop __syncthreads joins.
__global__ void __launch_bounds__(256) gru_phase(GG ga, GG gb) {
    extern __shared__ float sm[];
    float* ws = sm;                         // 96 x WP
    float* hs = sm + 96 * WP;               // 16 x HP
    float* red = sm + 96 * WP + 16 * HP;    // 128 x 13 (pad-13: conflict-free)

    GG g;
    int sgrp, mychunk;
    {
        int b = blockIdx.x;
        int blocks0 = ga.nsg * 8;
        if (b < blocks0) { g = ga; sgrp = b >> 3; mychunk = b & 7; }
        else { g = gb; int bb = b - blocks0; sgrp = bb >> 3; mychunk = bb & 7; }
    }
    const int colbase = mychunk * 32;
    unsigned* flags = &g_flag[(g.slotbase + sgrp) * 8 * 32];
    const int tid = threadIdx.x;
    const int warp = tid >> 5, lane = tid & 31;
    const int kw = warp >> 2, cw = warp & 3;
    const int c8 = lane & 7, sq = lane >> 3;
    const int widx = cw * 8 + c8;   // col within chunk, 0..31
    const int col = colbase + widx;

    for (int i = tid; i < 96 * 64; i += 256) {
        int r = i >> 6, q = i & 63;
        float4 v = __ldg(reinterpret_cast<const float4*>(
            &g.whh[(long long)((r >> 5) * 256 + colbase + (r & 31)) * 256 + q * 4]));
        *reinterpret_cast<float4*>(&ws[r * WP + q * 4]) = v;
    }
    const float br = g.bhh[col], bz = g.bhh[256 + col], bn = g.bhh[512 + col];
    float mx[4] = {-1e30f, -1e30f, -1e30f, -1e30f};

    const ulonglong2* wR = reinterpret_cast<const ulonglong2*>(&ws[(0  + widx) * WP]);
    const ulonglong2* wZ = reinterpret_cast<const ulonglong2*>(&ws[(32 + widx) * WP]);
    const ulonglong2* wN = reinterpret_cast<const ulonglong2*>(&ws[(64 + widx) * WP]);
    const ulonglong2* hr_[4];
#pragma unroll
    for (int j = 0; j < 4; j++)
        hr_[j] = reinterpret_cast<const ulonglong2*>(&hs[(sq + 4 * j) * HP]);

    const int q0 = kw * 32, q1 = q0 + 32;
    const int T = g.T;

    for (int t = 0; t < T; t++) {
        __syncthreads();  // join: publish done (kw0), polls confirmed (kw1)
        const float* hin = (t & 1) ? g.h1 : g.h0;
        float* hout = (t & 1) ? g.h0 : g.h1;
        const float4* tb = reinterpret_cast<const float4*>(hin + (long long)sgrp * 16 * 256);
#pragma unroll
        for (int i = 0; i < 4; i++) {
            int idx = tid + i * 256;
            float4 v = __ldcg(tb + idx);
            *reinterpret_cast<float4*>(&hs[(idx >> 6) * HP + (idx & 63) * 4]) = v;
        }
        float xr[4], xz[4], xn[4];
        if (kw == 0) {
#pragma unroll
            for (int j = 0; j < 4; j++) {
                long long base = ((long long)(sgrp * 16 + sq + 4 * j) * T + t) * 768;
                xr[j] = __ldg(&g.xg[base + col]);
                xz[j] = __ldg(&g.xg[base + 256 + col]);
                xn[j] = __ldg(&g.xg[base + 512 + col]);
            }
        }
        __syncthreads();  // hs staged

        unsigned long long aR[4][2], aZ[4][2], aN[4][2];
#pragma unroll
        for (int j = 0; j < 4; j++) {
            aR[j][0] = aR[j][1] = 0ull;
            aZ[j][0] = aZ[j][1] = 0ull;
            aN[j][0] = aN[j][1] = 0ull;
        }
#pragma unroll 4
        for (int q = q0; q < q1; q++) {
            ulonglong2 r_ = wR[q], z_ = wZ[q], n_ = wN[q];
#pragma unroll
            for (int j = 0; j < 4; j++) {
                ulonglong2 h = hr_[j][q];
                FMA2(aR[j][0], r_.x, h.x); FMA2(aR[j][1], r_.y, h.y);
                FMA2(aZ[j][0], z_.x, h.x); FMA2(aZ[j][1], z_.y, h.y);
                FMA2(aN[j][0], n_.x, h.x); FMA2(aN[j][1], n_.y, h.y);
            }
        }
        float pr[4], pz[4], pn[4];
#pragma unroll
        for (int j = 0; j < 4; j++) {
            pr[j] = red2(aR[j][0], aR[j][1]);
            pz[j] = red2(aZ[j][0], aZ[j][1]);
            pn[j] = red2(aN[j][0], aN[j][1]);
        }
        if (kw == 1) {
            float* rp = &red[(tid - 128) * 13];
#pragma unroll
            for (int j = 0; j < 4; j++) {
                rp[j] = pr[j]; rp[4 + j] = pz[j]; rp[8 + j] = pn[j];
            }
        }
        __syncthreads();  // partials visible
        if (kw == 0) {
            const float* rp = &red[tid * 13];
#pragma unroll
            for (int j = 0; j < 4; j++) {
                int sl = sq + 4 * j;
                long long seq = sgrp * 16 + sl;
                float hrv = pr[j] + rp[j] + br;
                float hzv = pz[j] + rp[4 + j] + bz;
                float hnv = pn[j] + rp[8 + j] + bn;
                // fast overflow-safe gates
                float er = __expf(-(xr[j] + hrv));
                float r = __fdividef(1.f, 1.f + er);
                float ez = __expf(-(xz[j] + hzv));
                float z = __fdividef(1.f, 1.f + ez);
                float e2 = __expf(2.f * (xn[j] + r * hnv));
                float n = 1.f - __fdividef(2.f, e2 + 1.f);
                float hold = hs[sl * HP + col];
                float h = (1.f - z) * n + z * hold;
                hout[seq * 256 + col] = h;
                if (g.ys) g.ys[((long long)seq * T + t) * g.ysld + col] = h;
                mx[j] = fmaxf(mx[j], h);
            }
            asm volatile("bar.sync 1, 128;" ::: "memory");
            if (tid == 0 && t + 1 < T) {
                __threadfence();
                st_rlx(&flags[mychunk * 32], (unsigned)(t + 1));
            }
        } else {
            if (t + 1 < T && tid < 136) {
                while (ld_acq(&flags[(tid - 128) * 32]) < (unsigned)(t + 1)) {}
            }
        }
    }
    if (g.hmax && kw == 0) {
#pragma unroll
        for (int j = 0; j < 4; j++) {
            long long seq = sgrp * 16 + sq + 4 * j;
            g.hmax[seq * 256 + col] = mx[j];
        }
    }
}

// ---------------- final: coef gate, feat, output head, softmax over options ----------------
__global__ void __launch_bounds__(512) final_kernel(
    const float* __restrict__ gate_w, const float* __restrict__ gate_b,
    const float* __restrict__ out_w, const float* __restrict__ out_b,
    float* __restrict__ out) {
    __shared__ float coef[128];
    __shared__ float logits[16];
    int tid = threadIdx.x, w = tid >> 5, lane = tid & 31;
    for (int bon = w; bon < 128; bon += 16) {
        float s = 0.f;
        for (int d = lane; d < 512; d += 32) {
            float rv = (d < 256) ? g_srmax[bon * 256 + d] : g_drmax[bon * 256 + d - 256];
            s += rv * gate_w[d];
        }
#pragma unroll
        for (int off = 16; off; off >>= 1) s += __shfl_xor_sync(0xffffffffu, s, off);
        if (lane == 0) coef[bon] = s + gate_b[0];
    }
    __syncthreads();
    {
        int bo = w;
        float acc = 0.f;
        for (int d = lane; d < 1024; d += 32) {
            float v;
            if (d < 512) {
                float mxv = -1e30f;
#pragma unroll
                for (int n = 0; n < 8; n++) {
                    int bon = bo * 8 + n;
                    float rv = (d < 256) ? g_srmax[bon * 256 + d] : g_drmax[bon * 256 + d - 256];
                    mxv = fmaxf(mxv, coef[bon] * rv);
                }
                v = mxv;
            } else {
                int dd = d - 512;
                float smv = 0.f;
#pragma unroll
                for (int n = 0; n < 8; n++) {
                    int bon = bo * 8 + n;
                    float rv = (dd < 256) ? g_srmax[bon * 256 + dd] : g_drmax[bon * 256 + dd - 256];
                    smv += coef[bon] * rv;
                }
                v = smv * 0.125f;
            }
            acc += v * out_w[d];
        }
#pragma unroll
        for (int off = 16; off; off >>= 1) acc += __shfl_xor_sync(0xffffffffu, acc, off);
        if (lane == 0) logits[bo] = acc + out_b[0];
    }
    __syncthreads();
    if (tid < 4) {
        int b = tid;
        float m = -1e30f;
        for (int o = 0; o < 4; o++) m = fmaxf(m, logits[b * 4 + o]);
        float e[4], s = 0.f;
        for (int o = 0; o < 4; o++) { e[o] = expf(logits[b * 4 + o] - m); s += e[o]; }
        for (int o = 0; o < 4; o++) out[b * 4 + o] = e[o] / s;
    }
}

// ---------------- host orchestration ----------------
#define SYM(p, s) do { void* _t = nullptr; cudaGetSymbolAddress(&_t, s); p = (float*)_t; } while (0)

static const int GRU_SMEM = (96 * WP + 16 * HP + 128 * 13) * 4;  // 123,136 B
static const int GEMM_SMEM = 4 * 4608 * 4;                        // 73,728 B

extern "C" void kernel_launch(void* const* d_in, const int* in_sizes, int n_in,
                              void* d_out, int out_size) {
    const float* statement = (const float*)d_in[0];
    const float* answer    = (const float*)d_in[1];
    const float* refs      = (const float*)d_in[2];
    const float* ctx_wih   = (const float*)d_in[3];
    const float* ctx_whh   = (const float*)d_in[4];
    const float* ctx_bih   = (const float*)d_in[5];
    const float* ctx_bhh   = (const float*)d_in[6];
    const float* sr_wih    = (const float*)d_in[7];
    const float* sr_whh    = (const float*)d_in[8];
    const float* sr_bih    = (const float*)d_in[9];
    const float* sr_bhh    = (const float*)d_in[10];
    const float* dr_wih    = (const float*)d_in[11];
    const float* dr_whh    = (const float*)d_in[12];
    const float* dr_bih    = (const float*)d_in[13];
    const float* dr_bhh    = (const float*)d_in[14];
    const float* gate_w    = (const float*)d_in[15];
    const float* gate_b    = (const float*)d_in[16];
    const float* out_w     = (const float*)d_in[17];
    const float* out_b     = (const float*)d_in[18];
    float* out = (float*)d_out;

    float *stmt_in, *xg_stmt, *stmt_h, *xg_docs;
    float *hs0, *hs1, *hd0, *hd1;
    float *matchb, *p1, *p2t, *read_sum, *dri, *mmb, *att;
    float *xg_sr, *xg_dr, *hsr0, *hsr1, *hdr0, *hdr1, *srmax, *drmax;
    SYM(stmt_in, g_stmt_in); SYM(xg_stmt, g_xg_stmt); SYM(stmt_h, g_stmt_h);
    SYM(xg_docs, g_xg_docs);
    SYM(hs0, g_hs0); SYM(hs1, g_hs1); SYM(hd0, g_hd0); SYM(hd1, g_hd1);
    SYM(matchb, g_match); SYM(p1, g_p1); SYM(p2t, g_p2t);
    SYM(read_sum, g_read_sum); SYM(dri, g_dri);
    SYM(mmb, g_mm); SYM(att, g_att);
    SYM(xg_sr, g_xg_sr); SYM(xg_dr, g_xg_dr);
    SYM(hsr0, g_hsr0); SYM(hsr1, g_hsr1); SYM(hdr0, g_hdr0); SYM(hdr1, g_hdr1);
    SYM(srmax, g_srmax); SYM(drmax, g_drmax);

    cudaFuncSetAttribute(gru_phase, cudaFuncAttributeMaxDynamicSharedMemorySize, GRU_SMEM);
    cudaFuncSetAttribute(gemm_tf32<0>, cudaFuncAttributeMaxDynamicSharedMemorySize, GEMM_SMEM);
    cudaFuncSetAttribute(gemm_tf32<1>, cudaFuncAttributeMaxDynamicSharedMemorySize, GEMM_SMEM);

    init_state<<<128, 256>>>();
    concat_stmt<<<4096, 256>>>(statement, answer);

    // input projections for ctx GRU (TN: W is [768, in])
    gemm_tf32<1><<<dim3(6, 32, 1), 256, GEMM_SMEM>>>(
        stmt_in, ctx_wih, ctx_bih, xg_stmt, 768, 256, 256, 256, 768, 0, 0, 0, 1, 1);
    gemm_tf32<1><<<dim3(6, 128, 1), 256, GEMM_SMEM>>>(
        refs, ctx_wih, ctx_bih, xg_docs, 768, 256, 256, 256, 768, 0, 0, 0, 1, 1);

    // phase A: ctx GRU — stmt (16 seqs, T=256) || docs (128 seqs, T=128)
    // docs ys writes DIRECTLY into dri[:, :, 0:256] (row pitch 512)
    {
        GG gs; gs.xg = xg_stmt; gs.whh = ctx_whh; gs.bhh = ctx_bhh;
        gs.h0 = hs0; gs.h1 = hs1; gs.ys = stmt_h; gs.hmax = nullptr;
        gs.T = 256; gs.nsg = 1; gs.slotbase = 0; gs.ysld = 256;
        GG gd; gd.xg = xg_docs; gd.whh = ctx_whh; gd.bhh = ctx_bhh;
        gd.h0 = hd0; gd.h1 = hd1; gd.ys = dri; gd.hmax = nullptr;
        gd.T = 128; gd.nsg = 8; gd.slotbase = 8; gd.ysld = 512;
        gru_phase<<<72, 256, GRU_SMEM>>>(gs, gd);
    }

    // match[bon][s][l] = stmt[bo,s,:] . docs[bon,l,:]   (docs live in dri, ldb=512)
    gemm_tf32<1><<<dim3(1, 2, 128), 256, GEMM_SMEM>>>(
        stmt_h, dri, nullptr, matchb, 128, 256, 256, 512, 128, 65536, 65536, 32768, 8, 1);
    softmax_warp128<<<4096, 256>>>(matchb, p1);
    softmax_cols_t<<<dim3(32, 128), 128>>>();
    // read_sum = p1 @ docs ; doc_read = p2t @ stmt -> dri[:, :, 256:512]
    gemm_tf32<0><<<dim3(2, 2, 128), 256, GEMM_SMEM>>>(
        p1, dri, nullptr, read_sum, 256, 128, 128, 512, 256, 32768, 65536, 65536, 1, 1);
    gemm_tf32<0><<<dim3(2, 1, 128), 256, GEMM_SMEM>>>(
        p2t, stmt_h, nullptr, dri + 256, 256, 256, 256, 256, 512, 32768, 65536, 65536, 1, 8);

    // doc-doc cross attention per bo: mm = dri @ dri^T ; softmax ; att = p3 @ dri
    gemm_tf32<1><<<dim3(8, 8, 16), 256, GEMM_SMEM>>>(
        dri, dri, nullptr, mmb, 1024, 512, 512, 512, 1024, 524288, 524288, 1048576, 1, 1);
    softmax_block1024<<<16384, 256>>>(mmb, mmb);
    gemm_tf32<0><<<dim3(4, 8, 16), 256, GEMM_SMEM>>>(
        mmb, dri, nullptr, att, 512, 1024, 1024, 512, 512, 1048576, 524288, 524288, 1, 1);

    // input projections for reasoning GRUs
    gemm_tf32<1><<<dim3(6, 256, 1), 256, GEMM_SMEM>>>(
        read_sum, sr_wih, sr_bih, xg_sr, 768, 256, 256, 256, 768, 0, 0, 0, 1, 1);
    gemm_tf32<1><<<dim3(6, 128, 1), 256, GEMM_SMEM>>>(
        att, dr_wih, dr_bih, xg_dr, 768, 512, 512, 512, 768, 0, 0, 0, 1, 1);

    // phase C: reasoning GRUs — sr (128 seqs, T=256) || dr (128 seqs, T=128)
    {
        GG ga; ga.xg = xg_sr; ga.whh = sr_whh; ga.bhh = sr_bhh;
        ga.h0 = hsr0; ga.h1 = hsr1; ga.ys = nullptr; ga.hmax = srmax;
        ga.T = 256; ga.nsg = 8; ga.slotbase = 32; ga.ysld = 0;
        GG gb; gb.xg = xg_dr; gb.whh = dr_whh; gb.bhh = dr_bhh;
        gb.h0 = hdr0; gb.h1 = hdr1; gb.ys = nullptr; gb.hmax = drmax;
        gb.T = 128; gb.nsg = 8; gb.slotbase = 48; gb.ysld = 0;
        gru_phase<<<128, 256, GRU_SMEM>>>(ga, gb);
    }

    final_kernel<<<1, 512>>>(gate_w, gate_b, out_w, out_b, out);
}

// round 15
// speedup vs baseline: 1.9114x; 1.2351x over previous
#include <cuda_runtime.h>
#include <math.h>

// Problem dims: B=4 O=4 L=128 N=8 V=256 H=256, Ls=2L=256, BO=16, BON=128, NL=1024

// ---------------- scratch (device globals; no allocation allowed) ----------------
__device__ float g_stmt_in[16 * 256 * 256];
__device__ float g_xg_stmt[16 * 256 * 768];
__device__ float g_stmt_h[16 * 256 * 256];
__device__ float g_xg_docs[128 * 128 * 768];
__device__ float g_hs0[16 * 256], g_hs1[16 * 256];
__device__ float g_hd0[128 * 256], g_hd1[128 * 256];
__device__ float g_match[128 * 256 * 128];
__device__ float g_p1[128 * 256 * 128];
__device__ float g_p2t[128 * 128 * 256];
__device__ float g_read_sum[128 * 256 * 256];
__device__ float g_dri[128 * 128 * 512];
__device__ float g_mm[16 * 1024 * 1024];
__device__ float g_att[128 * 128 * 512];
__device__ float g_xg_sr[128 * 256 * 768];
__device__ float g_xg_dr[128 * 128 * 768];
__device__ float g_hsr0[128 * 256], g_hsr1[128 * 256];
__device__ float g_hdr0[128 * 256], g_hdr1[128 * 256];
__device__ float g_srmax[128 * 256], g_drmax[128 * 256];

// per-(slot, chunk) monotonic step flags: 64 slots x 8 chunks, 128B stride
__device__ unsigned g_flag[64 * 8 * 32];

// ---------------- init ----------------
__global__ void init_state() {
    int i = blockIdx.x * 256 + threadIdx.x;  // 32768 threads
    if (i < 64 * 8 * 32) g_flag[i] = 0u;
    if (i < 16 * 256) { g_hs0[i] = 0.f; g_hs1[i] = 0.f; }
    if (i < 128 * 256) {
        g_hd0[i] = 0.f;  g_hd1[i] = 0.f;
        g_hsr0[i] = 0.f; g_hsr1[i] = 0.f;
        g_hdr0[i] = 0.f; g_hdr1[i] = 0.f;
    }
}

// ---------------- build stmt = cat(question, answer) ----------------
__global__ void concat_stmt(const float* __restrict__ statement,
                            const float* __restrict__ answer) {
    int idx = blockIdx.x * 256 + threadIdx.x;  // 1048576
    int v = idx & 255;
    int s = (idx >> 8) & 255;
    int bo = idx >> 16;
    int b = bo >> 2;
    float val;
    if (s < 128) val = statement[(b * 128 + s) * 256 + v];
    else         val = answer[(bo * 128 + (s - 128)) * 256 + v];
    g_stmt_in[idx] = val;
}

// ---------------- cp.async helpers ----------------
__device__ __forceinline__ unsigned smem_u32(const void* p) {
    return (unsigned)__cvta_generic_to_shared(p);
}
__device__ __forceinline__ void cp16(unsigned dst, const void* src) {
    asm volatile("cp.async.cg.shared.global [%0], [%1], 16;" :: "r"(dst), "l"(src));
}
template <int n> __device__ __forceinline__ void cp_wait() {
    asm volatile("cp.async.wait_group %0;" :: "n"(n) : "memory");
}

__device__ __forceinline__ void mma_tf32(float4& d, const unsigned* a, const unsigned* b) {
    asm volatile(
        "mma.sync.aligned.m16n8k8.row.col.f32.tf32.tf32.f32 "
        "{%0,%1,%2,%3}, {%4,%5,%6,%7}, {%8,%9}, {%0,%1,%2,%3};"
        : "+f"(d.x), "+f"(d.y), "+f"(d.z), "+f"(d.w)
        : "r"(a[0]), "r"(a[1]), "r"(a[2]), "r"(a[3]), "r"(b[0]), "r"(b[1]));
}

// Tile 128x128, K-tile 32, 256 threads, cp.async double-buffered, 2 blocks/SM.
// Raw fp32 bits fed to tf32 MMA (HW truncation).
// TB=1: C = A[M,K] * B[N,K]^T (+bias);  TB=0: C = A[M,K] * B[K,N] (+bias)
template <int TB>
__global__ void __launch_bounds__(256, 2) gemm_tf32(
    const float* __restrict__ A, const float* __restrict__ B,
    const float* __restrict__ bias, float* __restrict__ C,
    int N, int K, int lda, int ldb, int ldc,
    long long sA, long long sB, long long sC, int divA, int divB) {
    extern __shared__ unsigned gsm[];
    unsigned* Abuf[2] = {gsm, gsm + 4608};
    unsigned* Bbuf[2] = {gsm + 9216, gsm + 13824};

    const int tid = threadIdx.x;
    int z = blockIdx.z;
    A += (long long)(z / divA) * sA + (long long)(blockIdx.y * 128) * lda;
    if (TB) B += (long long)(z / divB) * sB + (long long)(blockIdx.x * 128) * ldb;
    else    B += (long long)(z / divB) * sB + blockIdx.x * 128;
    C += (long long)z * sC + (long long)(blockIdx.y * 128) * ldc + blockIdx.x * 128;

    const int warp = tid >> 5, lane = tid & 31;
    const int wm = (warp & 1) * 64, wn = (warp >> 1) * 32;
    const int lq = lane >> 2, lr = lane & 3;
    const int sm_ = tid >> 3;        // 0..31 (+32*i)
    const int sk = (tid & 7) * 4;    // 0..28
    const int bk = tid >> 5;         // 0..7 (+8*i)
    const int bn = (tid & 31) * 4;   // 0..124

    float4 acc[4][4];
#pragma unroll
    for (int i = 0; i < 4; i++)
#pragma unroll
        for (int j = 0; j < 4; j++) acc[i][j] = make_float4(0.f, 0.f, 0.f, 0.f);

    auto issue = [&](int s, int k0) {
        unsigned* As = Abuf[s];
        unsigned* Bs = Bbuf[s];
#pragma unroll
        for (int i = 0; i < 4; i++)
            cp16(smem_u32(&As[(sm_ + 32 * i) * 36 + sk]),
                 &A[(long long)(sm_ + 32 * i) * lda + k0 + sk]);
        if (TB) {
#pragma unroll
            for (int i = 0; i < 4; i++)
                cp16(smem_u32(&Bs[(sm_ + 32 * i) * 36 + sk]),
                     &B[(long long)(sm_ + 32 * i) * ldb + k0 + sk]);
        } else {
#pragma unroll
            for (int i = 0; i < 4; i++)
                cp16(smem_u32(&Bs[(bk + 8 * i) * 132 + bn]),
                     &B[(long long)(k0 + bk + 8 * i) * ldb + bn]);
        }
        asm volatile("cp.async.commit_group;" ::: "memory");
    };

    const int NT = K >> 5;
    issue(0, 0);
    for (int it = 0; it < NT; it++) {
        const int s = it & 1;
        if (it + 1 < NT) { issue(s ^ 1, (it + 1) * 32); cp_wait<1>(); }
        else cp_wait<0>();
        __syncthreads();
        const unsigned* As = Abuf[s];
        const unsigned* Bs = Bbuf[s];
#pragma unroll
        for (int kk = 0; kk < 32; kk += 8) {
            unsigned a[4][4];
#pragma unroll
            for (int mt = 0; mt < 4; mt++) {
                int r = (wm + mt * 16 + lq) * 36 + kk + lr;
                a[mt][0] = As[r];
                a[mt][1] = As[r + 8 * 36];
                a[mt][2] = As[r + 4];
                a[mt][3] = As[r + 8 * 36 + 4];
            }
            unsigned b[4][2];
#pragma unroll
            for (int nt = 0; nt < 4; nt++) {
                if (TB) {
                    int r = (wn + nt * 8 + lq) * 36 + kk + lr;
                    b[nt][0] = Bs[r];
                    b[nt][1] = Bs[r + 4];
                } else {
                    int r = (kk + lr) * 132 + wn + nt * 8 + lq;
                    b[nt][0] = Bs[r];
                    b[nt][1] = Bs[r + 4 * 132];
                }
            }
#pragma unroll
            for (int mt = 0; mt < 4; mt++)
#pragma unroll
                for (int nt = 0; nt < 4; nt++) mma_tf32(acc[mt][nt], a[mt], b[nt]);
        }
        __syncthreads();
    }

#pragma unroll
    for (int nt = 0; nt < 4; nt++) {
        int col = wn + nt * 8 + 2 * lr;
        float bx = 0.f, by = 0.f;
        if (bias) {
            int cg = blockIdx.x * 128 + col;
            bx = bias[cg]; by = bias[cg + 1];
        }
#pragma unroll
        for (int mt = 0; mt < 4; mt++) {
            int row = wm + mt * 16 + lq;
            float4 v = acc[mt][nt];
            float2 v0 = make_float2(v.x + bx, v.y + by);
            float2 v1 = make_float2(v.z + bx, v.w + by);
            *reinterpret_cast<float2*>(&C[(long long)row * ldc + col]) = v0;
            *reinterpret_cast<float2*>(&C[(long long)(row + 8) * ldc + col]) = v1;
        }
    }
}

// ---------------- softmax: 1024 cols, block per row, regs-resident ----------------
__global__ void __launch_bounds__(256) softmax_block1024(const float* __restrict__ in,
                                                         float* __restrict__ out) {
    long long row = blockIdx.x;
    const float4* x = reinterpret_cast<const float4*>(in + row * 1024);
    float4* y = reinterpret_cast<float4*>(out + row * 1024);
    int tid = threadIdx.x, warp = tid >> 5, lane = tid & 31;
    __shared__ float redm[8], reds[8];
    float4 v = x[tid];
    float m = fmaxf(fmaxf(v.x, v.y), fmaxf(v.z, v.w));
#pragma unroll
    for (int off = 16; off; off >>= 1) m = fmaxf(m, __shfl_xor_sync(0xffffffffu, m, off));
    if (lane == 0) redm[warp] = m;
    __syncthreads();
    m = redm[0];
#pragma unroll
    for (int i = 1; i < 8; i++) m = fmaxf(m, redm[i]);
    v.x = __expf(v.x - m); v.y = __expf(v.y - m); v.z = __expf(v.z - m); v.w = __expf(v.w - m);
    float s = v.x + v.y + v.z + v.w;
#pragma unroll
    for (int off = 16; off; off >>= 1) s += __shfl_xor_sync(0xffffffffu, s, off);
    if (lane == 0) reds[warp] = s;
    __syncthreads();
    s = reds[0];
#pragma unroll
    for (int i = 1; i < 8; i++) s += reds[i];
    float inv = 1.f / s;
    v.x *= inv; v.y *= inv; v.z *= inv; v.w *= inv;
    y[tid] = v;
}

// ---------------- softmax: 128 cols, warp per row (8 rows per block) ----------------
__global__ void __launch_bounds__(256) softmax_warp128(const float* __restrict__ in,
                                                       float* __restrict__ out) {
    int warp = threadIdx.x >> 5, lane = threadIdx.x & 31;
    long long row = (long long)blockIdx.x * 8 + warp;
    const float4* x = reinterpret_cast<const float4*>(in + row * 128);
    float4* y = reinterpret_cast<float4*>(out + row * 128);
    float4 v = x[lane];
    float m = fmaxf(fmaxf(v.x, v.y), fmaxf(v.z, v.w));
#pragma unroll
    for (int off = 16; off; off >>= 1) m = fmaxf(m, __shfl_xor_sync(0xffffffffu, m, off));
    v.x = __expf(v.x - m); v.y = __expf(v.y - m); v.z = __expf(v.z - m); v.w = __expf(v.w - m);
    float s = v.x + v.y + v.z + v.w;
#pragma unroll
    for (int off = 16; off; off >>= 1) s += __shfl_xor_sync(0xffffffffu, s, off);
    float inv = 1.f / s;
    v.x *= inv; v.y *= inv; v.z *= inv; v.w *= inv;
    y[lane] = v;
}

// ---------------- column softmax of match over s, output transposed [bon][l][s] ----------------
__global__ void __launch_bounds__(128) softmax_cols_t() {
    int bon = blockIdx.y;
    int l = blockIdx.x * 4 + (threadIdx.x >> 5);
    int lane = threadIdx.x & 31;
    const float* base = g_match + (long long)bon * 256 * 128 + l;
    float v[8];
    float m = -1e30f;
#pragma unroll
    for (int i = 0; i < 8; i++) {
        v[i] = base[(lane + 32 * i) * 128];
        m = fmaxf(m, v[i]);
    }
#pragma unroll
    for (int off = 16; off; off >>= 1) m = fmaxf(m, __shfl_xor_sync(0xffffffffu, m, off));
    float sum = 0.f;
#pragma unroll
    for (int i = 0; i < 8; i++) { v[i] = __expf(v[i] - m); sum += v[i]; }
#pragma unroll
    for (int off = 16; off; off >>= 1) sum += __shfl_xor_sync(0xffffffffu, sum, off);
    float inv = 1.f / sum;
    float* o = g_p2t + ((long long)bon * 128 + l) * 256;
#pragma unroll
    for (int i = 0; i < 8; i++) o[lane + 32 * i] = v[i] * inv;
}

// ---------------- acquire/relaxed flag ops ----------------
__device__ __forceinline__ unsigned ld_acq(const unsigned* p) {
    unsigned v;
    asm volatile("ld.global.acquire.gpu.u32 %0, [%1];" : "=r"(v) : "l"(p) : "memory");
    return v;
}
__device__ __forceinline__ void st_rlx(unsigned* p, unsigned v) {
    asm volatile("st.global.relaxed.gpu.u32 [%0], %1;" :: "l"(p), "r"(v) : "memory");
}

// ---------------- persistent fused GRU phase (tensor-core step GEMM) ----------------
struct GG {
    const float* xg;    // [nseq][T][768]
    const float* whh;   // [768][256]
    const float* bhh;   // [768]
    float* h0;          // [nseq][256] (t even input)
    float* h1;
    float* ys;          // optional [nseq][T][ysld]
    float* hmax;        // optional [nseq][256]
    int T;
    int nsg;            // seq groups of 16
    int slotbase;       // flag slot base (one slot per sgrp)
    int ysld;           // ys row pitch (floats)
};

#define WP 260  // weight row pitch (floats); 260 % 32 == 4 -> frag banks lq*4+lr distinct
#define HP 260  // h row pitch

// block = 256 threads (8 warps), tile = 16 seqs x 32 cols (one col chunk).
// Step GEMM M=16 N=96(3 gates x 32 cols) K=256 done with mma.m16n8k8 tf32.
// nw = warp&3 owns col-tile nw (8 cols, all 3 gates); kw = warp>>2 takes half of K.
// Cross-kw partials merged through smem (SCALAR stores: pad-13 stride is only
// 4B-aligned, v4 smem ops would trap). Sync protocol identical to proven R12/R13:
// kw0 gate math + stores + named barrier + publish; kw1 concurrently polls.
__global__ void __launch_bounds__(256) gru_phase(GG ga, GG gb) {
    extern __shared__ float sm[];
    float* ws = sm;                         // 96 x WP
    float* hs = sm + 96 * WP;               // 16 x HP
    float* red = sm + 96 * WP + 16 * HP;    // 128 x 13 (pad-13: conflict-free)

    GG g;
    int sgrp, mychunk;
    {
        int b = blockIdx.x;
        int blocks0 = ga.nsg * 8;
        if (b < blocks0) { g = ga; sgrp = b >> 3; mychunk = b & 7; }
        else { g = gb; int bb = b - blocks0; sgrp = bb >> 3; mychunk = bb & 7; }
    }
    const int colbase = mychunk * 32;
    unsigned* flags = &g_flag[(g.slotbase + sgrp) * 8 * 32];
    const int tid = threadIdx.x;
    const int warp = tid >> 5, lane = tid & 31;
    const int kw = warp >> 2, nw = warp & 3;
    const int lq = lane >> 2, lr = lane & 3;
    const int col0 = colbase + nw * 8 + 2 * lr;  // pair (col0, col0+1)

    // load weight slice: ws row r = gate*32 + j holds whh[gate*256 + colbase + j][:]
    for (int i = tid; i < 96 * 64; i += 256) {
        int r = i >> 6, q = i & 63;
        float4 v = __ldg(reinterpret_cast<const float4*>(
            &g.whh[(long long)((r >> 5) * 256 + colbase + (r & 31)) * 256 + q * 4]));
        *reinterpret_cast<float4*>(&ws[r * WP + q * 4]) = v;
    }
    // biases for the two cols, all 3 gates
    const float br0 = g.bhh[col0],       br1 = g.bhh[col0 + 1];
    const float bz0 = g.bhh[256 + col0], bz1 = g.bhh[256 + col0 + 1];
    const float bn0 = g.bhh[512 + col0], bn1 = g.bhh[512 + col0 + 1];
    float mx[2][2] = {{-1e30f, -1e30f}, {-1e30f, -1e30f}};

    const unsigned* hsu = reinterpret_cast<const unsigned*>(hs);
    const unsigned* wsu = reinterpret_cast<const unsigned*>(ws);
    const int kb0 = kw * 16;  // 16 k-blocks of 8 per kw half
    const int T = g.T;

    for (int t = 0; t < T; t++) {
        __syncthreads();  // join: publish done (kw0), polls confirmed (kw1)
        const float* hin = (t & 1) ? g.h1 : g.h0;
        float* hout = (t & 1) ? g.h0 : g.h1;
        const float4* tb = reinterpret_cast<const float4*>(hin + (long long)sgrp * 16 * 256);
#pragma unroll
        for (int i = 0; i < 4; i++) {
            int idx = tid + i * 256;
            float4 v = __ldcg(tb + idx);
            *reinterpret_cast<float4*>(&hs[(idx >> 6) * HP + (idx & 63) * 4]) = v;
        }
        // xg prefetch: 2 seq cells x 3 gates x col pair (float2, col0 even)
        float2 xr[2], xz[2], xn[2];
        if (kw == 0) {
#pragma unroll
            for (int i = 0; i < 2; i++) {
                long long base = ((long long)(sgrp * 16 + lq + 8 * i) * T + t) * 768;
                xr[i] = __ldg(reinterpret_cast<const float2*>(&g.xg[base + col0]));
                xz[i] = __ldg(reinterpret_cast<const float2*>(&g.xg[base + 256 + col0]));
                xn[i] = __ldg(reinterpret_cast<const float2*>(&g.xg[base + 512 + col0]));
            }
        }
        __syncthreads();  // hs staged

        float4 acc[3];
#pragma unroll
        for (int gte = 0; gte < 3; gte++) acc[gte] = make_float4(0.f, 0.f, 0.f, 0.f);
#pragma unroll 4
        for (int kb = 0; kb < 16; kb++) {
            int k8 = (kb0 + kb) * 8;
            unsigned a[4];
            int ra = lq * HP + k8 + lr;
            a[0] = hsu[ra];
            a[1] = hsu[ra + 8 * HP];
            a[2] = hsu[ra + 4];
            a[3] = hsu[ra + 8 * HP + 4];
#pragma unroll
            for (int gte = 0; gte < 3; gte++) {
                int rb = (gte * 32 + nw * 8 + lq) * WP + k8 + lr;
                unsigned b[2] = {wsu[rb], wsu[rb + 4]};
                mma_tf32(acc[gte], a, b);
            }
        }
        // merge kw halves through smem (12 SCALAR floats per thread; pad-13)
        if (kw == 1) {
            float* rp = &red[(tid - 128) * 13];
            rp[0] = acc[0].x; rp[1] = acc[0].y; rp[2]  = acc[0].z; rp[3]  = acc[0].w;
            rp[4] = acc[1].x; rp[5] = acc[1].y; rp[6]  = acc[1].z; rp[7]  = acc[1].w;
            rp[8] = acc[2].x; rp[9] = acc[2].y; rp[10] = acc[2].z; rp[11] = acc[2].w;
        }
        __syncthreads();  // partials visible
        if (kw == 0) {
            const float* rp = &red[tid * 13];
            float aR[4] = {acc[0].x + rp[0], acc[0].y + rp[1], acc[0].z + rp[2], acc[0].w + rp[3]};
            float aZ[4] = {acc[1].x + rp[4], acc[1].y + rp[5], acc[1].z + rp[6], acc[1].w + rp[7]};
            float aN[4] = {acc[2].x + rp[8], acc[2].y + rp[9], acc[2].z + rp[10], acc[2].w + rp[11]};
#pragma unroll
            for (int i = 0; i < 2; i++) {        // seq half: s = lq + 8i
                int s = lq + 8 * i;
                long long seq = sgrp * 16 + s;
#pragma unroll
                for (int j = 0; j < 2; j++) {    // col: col0 + j
                    int comp = 2 * i + j;
                    int col = col0 + j;
                    float hrv = aR[comp] + (j ? br1 : br0);
                    float hzv = aZ[comp] + (j ? bz1 : bz0);
                    float hnv = aN[comp] + (j ? bn1 : bn0);
                    float xrv = j ? xr[i].y : xr[i].x;
                    float xzv = j ? xz[i].y : xz[i].x;
                    float xnv = j ? xn[i].y : xn[i].x;
                    float er = __expf(-(xrv + hrv));
                    float r = __fdividef(1.f, 1.f + er);
                    float ez = __expf(-(xzv + hzv));
                    float z = __fdividef(1.f, 1.f + ez);
                    float e2 = __expf(2.f * (xnv + r * hnv));
                    float n = 1.f - __fdividef(2.f, e2 + 1.f);
                    float hold = hs[s * HP + col];
                    float h = (1.f - z) * n + z * hold;
                    hout[seq * 256 + col] = h;
                    if (g.ys) g.ys[((long long)seq * T + t) * g.ysld + col] = h;
                    mx[i][j] = fmaxf(mx[i][j], h);
                }
            }
            asm volatile("bar.sync 1, 128;" ::: "memory");
            if (tid == 0 && t + 1 < T) {
                __threadfence();
                st_rlx(&flags[mychunk * 32], (unsigned)(t + 1));
            }
        } else {
            if (t + 1 < T && tid < 136) {
                while (ld_acq(&flags[(tid - 128) * 32]) < (unsigned)(t + 1)) {}
            }
        }
    }
    if (g.hmax && kw == 0) {
#pragma unroll
        for (int i = 0; i < 2; i++)
#pragma unroll
            for (int j = 0; j < 2; j++) {
                long long seq = sgrp * 16 + lq + 8 * i;
                g.hmax[seq * 256 + col0 + j] = mx[i][j];
            }
    }
}

// ---------------- final: coef gate, feat, output head, softmax over options ----------------
__global__ void __launch_bounds__(512) final_kernel(
    const float* __restrict__ gate_w, const float* __restrict__ gate_b,
    const float* __restrict__ out_w, const float* __restrict__ out_b,
    float* __restrict__ out) {
    __shared__ float coef[128];
    __shared__ float logits[16];
    int tid = threadIdx.x, w = tid >> 5, lane = tid & 31;
    for (int bon = w; bon < 128; bon += 16) {
        float s = 0.f;
        for (int d = lane; d < 512; d += 32) {
            float rv = (d < 256) ? g_srmax[bon * 256 + d] : g_drmax[bon * 256 + d - 256];
            s += rv * gate_w[d];
        }
#pragma unroll
        for (int off = 16; off; off >>= 1) s += __shfl_xor_sync(0xffffffffu, s, off);
        if (lane == 0) coef[bon] = s + gate_b[0];
    }
    __syncthreads();
    {
        int bo = w;
        float acc = 0.f;
        for (int d = lane; d < 1024; d += 32) {
            float v;
            if (d < 512) {
                float mxv = -1e30f;
#pragma unroll
                for (int n = 0; n < 8; n++) {
                    int bon = bo * 8 + n;
                    float rv = (d < 256) ? g_srmax[bon * 256 + d] : g_drmax[bon * 256 + d - 256];
                    mxv = fmaxf(mxv, coef[bon] * rv);
                }
                v = mxv;
            } else {
                int dd = d - 512;
                float smv = 0.f;
#pragma unroll
                for (int n = 0; n < 8; n++) {
                    int bon = bo * 8 + n;
                    float rv = (dd < 256) ? g_srmax[bon * 256 + dd] : g_drmax[bon * 256 + dd - 256];
                    smv += coef[bon] * rv;
                }
                v = smv * 0.125f;
            }
            acc += v * out_w[d];
        }
#pragma unroll
        for (int off = 16; off; off >>= 1) acc += __shfl_xor_sync(0xffffffffu, acc, off);
        if (lane == 0) logits[bo] = acc + out_b[0];
    }
    __syncthreads();
    if (tid < 4) {
        int b = tid;
        float m = -1e30f;
        for (int o = 0; o < 4; o++) m = fmaxf(m, logits[b * 4 + o]);
        float e[4], s = 0.f;
        for (int o = 0; o < 4; o++) { e[o] = expf(logits[b * 4 + o] - m); s += e[o]; }
        for (int o = 0; o < 4; o++) out[b * 4 + o] = e[o] / s;
    }
}

// ---------------- host orchestration ----------------
#define SYM(p, s) do { void* _t = nullptr; cudaGetSymbolAddress(&_t, s); p = (float*)_t; } while (0)

static const int GRU_SMEM = (96 * WP + 16 * HP + 128 * 13) * 4;  // 123,136 B
static const int GEMM_SMEM = 4 * 4608 * 4;                        // 73,728 B

extern "C" void kernel_launch(void* const* d_in, const int* in_sizes, int n_in,
                              void* d_out, int out_size) {
    const float* statement = (const float*)d_in[0];
    const float* answer    = (const float*)d_in[1];
    const float* refs      = (const float*)d_in[2];
    const float* ctx_wih   = (const float*)d_in[3];
    const float* ctx_whh   = (const float*)d_in[4];
    const float* ctx_bih   = (const float*)d_in[5];
    const float* ctx_bhh   = (const float*)d_in[6];
    const float* sr_wih    = (const float*)d_in[7];
    const float* sr_whh    = (const float*)d_in[8];
    const float* sr_bih    = (const float*)d_in[9];
    const float* sr_bhh    = (const float*)d_in[10];
    const float* dr_wih    = (const float*)d_in[11];
    const float* dr_whh    = (const float*)d_in[12];
    const float* dr_bih    = (const float*)d_in[13];
    const float* dr_bhh    = (const float*)d_in[14];
    const float* gate_w    = (const float*)d_in[15];
    const float* gate_b    = (const float*)d_in[16];
    const float* out_w     = (const float*)d_in[17];
    const float* out_b     = (const float*)d_in[18];
    float* out = (float*)d_out;

    float *stmt_in, *xg_stmt, *stmt_h, *xg_docs;
    float *hs0, *hs1, *hd0, *hd1;
    float *matchb, *p1, *p2t, *read_sum, *dri, *mmb, *att;
    float *xg_sr, *xg_dr, *hsr0, *hsr1, *hdr0, *hdr1, *srmax, *drmax;
    SYM(stmt_in, g_stmt_in); SYM(xg_stmt, g_xg_stmt); SYM(stmt_h, g_stmt_h);
    SYM(xg_docs, g_xg_docs);
    SYM(hs0, g_hs0); SYM(hs1, g_hs1); SYM(hd0, g_hd0); SYM(hd1, g_hd1);
    SYM(matchb, g_match); SYM(p1, g_p1); SYM(p2t, g_p2t);
    SYM(read_sum, g_read_sum); SYM(dri, g_dri);
    SYM(mmb, g_mm); SYM(att, g_att);
    SYM(xg_sr, g_xg_sr); SYM(xg_dr, g_xg_dr);
    SYM(hsr0, g_hsr0); SYM(hsr1, g_hsr1); SYM(hdr0, g_hdr0); SYM(hdr1, g_hdr1);
    SYM(srmax, g_srmax); SYM(drmax, g_drmax);

    cudaFuncSetAttribute(gru_phase, cudaFuncAttributeMaxDynamicSharedMemorySize, GRU_SMEM);
    cudaFuncSetAttribute(gemm_tf32<0>, cudaFuncAttributeMaxDynamicSharedMemorySize, GEMM_SMEM);
    cudaFuncSetAttribute(gemm_tf32<1>, cudaFuncAttributeMaxDynamicSharedMemorySize, GEMM_SMEM);

    init_state<<<128, 256>>>();
    concat_stmt<<<4096, 256>>>(statement, answer);

    // input projections for ctx GRU (TN: W is [768, in])
    gemm_tf32<1><<<dim3(6, 32, 1), 256, GEMM_SMEM>>>(
        stmt_in, ctx_wih, ctx_bih, xg_stmt, 768, 256, 256, 256, 768, 0, 0, 0, 1, 1);
    gemm_tf32<1><<<dim3(6, 128, 1), 256, GEMM_SMEM>>>(
        refs, ctx_wih, ctx_bih, xg_docs, 768, 256, 256, 256, 768, 0, 0, 0, 1, 1);

    // phase A: ctx GRU — stmt (16 seqs, T=256) || docs (128 seqs, T=128)
    // docs ys writes DIRECTLY into dri[:, :, 0:256] (row pitch 512)
    {
        GG gs; gs.xg = xg_stmt; gs.whh = ctx_whh; gs.bhh = ctx_bhh;
        gs.h0 = hs0; gs.h1 = hs1; gs.ys = stmt_h; gs.hmax = nullptr;
        gs.T = 256; gs.nsg = 1; gs.slotbase = 0; gs.ysld = 256;
        GG gd; gd.xg = xg_docs; gd.whh = ctx_whh; gd.bhh = ctx_bhh;
        gd.h0 = hd0; gd.h1 = hd1; gd.ys = dri; gd.hmax = nullptr;
        gd.T = 128; gd.nsg = 8; gd.slotbase = 8; gd.ysld = 512;
        gru_phase<<<72, 256, GRU_SMEM>>>(gs, gd);
    }

    // match[bon][s][l] = stmt[bo,s,:] . docs[bon,l,:]   (docs live in dri, ldb=512)
    gemm_tf32<1><<<dim3(1, 2, 128), 256, GEMM_SMEM>>>(
        stmt_h, dri, nullptr, matchb, 128, 256, 256, 512, 128, 65536, 65536, 32768, 8, 1);
    softmax_warp128<<<4096, 256>>>(matchb, p1);
    softmax_cols_t<<<dim3(32, 128), 128>>>();
    // read_sum = p1 @ docs ; doc_read = p2t @ stmt -> dri[:, :, 256:512]
    gemm_tf32<0><<<dim3(2, 2, 128), 256, GEMM_SMEM>>>(
        p1, dri, nullptr, read_sum, 256, 128, 128, 512, 256, 32768, 65536, 65536, 1, 1);
    gemm_tf32<0><<<dim3(2, 1, 128), 256, GEMM_SMEM>>>(
        p2t, stmt_h, nullptr, dri + 256, 256, 256, 256, 256, 512, 32768, 65536, 65536, 1, 8);

    // doc-doc cross attention per bo: mm = dri @ dri^T ; softmax ; att = p3 @ dri
    gemm_tf32<1><<<dim3(8, 8, 16), 256, GEMM_SMEM>>>(
        dri, dri, nullptr, mmb, 1024, 512, 512, 512, 1024, 524288, 524288, 1048576, 1, 1);
    softmax_block1024<<<16384, 256>>>(mmb, mmb);
    gemm_tf32<0><<<dim3(4, 8, 16), 256, GEMM_SMEM>>>(
        mmb, dri, nullptr, att, 512, 1024, 1024, 512, 512, 1048576, 524288, 524288, 1, 1);

    // input projections for reasoning GRUs
    gemm_tf32<1><<<dim3(6, 256, 1), 256, GEMM_SMEM>>>(
        read_sum, sr_wih, sr_bih, xg_sr, 768, 256, 256, 256, 768, 0, 0, 0, 1, 1);
    gemm_tf32<1><<<dim3(6, 128, 1), 256, GEMM_SMEM>>>(
        att, dr_wih, dr_bih, xg_dr, 768, 512, 512, 512, 768, 0, 0, 0, 1, 1);

    // phase C: reasoning GRUs — sr (128 seqs, T=256) || dr (128 seqs, T=128)
    {
        GG ga; ga.xg = xg_sr; ga.whh = sr_whh; ga.bhh = sr_bhh;
        ga.h0 = hsr0; ga.h1 = hsr1; ga.ys = nullptr; ga.hmax = srmax;
        ga.T = 256; ga.nsg = 8; ga.slotbase = 32; ga.ysld = 0;
        GG gb; gb.xg = xg_dr; gb.whh = dr_whh; gb.bhh = dr_bhh;
        gb.h0 = hdr0; gb.h1 = hdr1; gb.ys = nullptr; gb.hmax = drmax;
        gb.T = 128; gb.nsg = 8; gb.slotbase = 48; gb.ysld = 0;
        gru_phase<<<128, 256, GRU_SMEM>>>(ga, gb);
    }

    final_kernel<<<1, 512>>>(gate_w, gate_b, out_w, out_b, out);
}